// round 3
// baseline (speedup 1.0000x reference)
#include <cuda_runtime.h>
#include <cstddef>

#define B_  8
#define L_  1024
#define H_  1024
#define K3_ 3072
#define N_  64

// Scratch (static __device__ — no allocations allowed)
__device__ float g_s [B_ * L_ * H_];   // projected samples   [b][l][h]   32 MB
__device__ float g_A [B_ * L_ * L_];   // graph -> softmax A  [b][l][m]   32 MB
__device__ float g_B0[B_ * L_ * N_];   // centered labels                2 MB
__device__ float g_u1[B_ * L_ * N_];
__device__ float g_u2[B_ * L_ * N_];

// ---------------------------------------------------------------------------
// NT GEMM: C[m,n] = sum_k X[m,k] * Y[n,k] (+ bias[n]).  Both operands row-major,
// K contiguous. 128x128 block tile, BK=16, 256 threads, 8x8 per thread.
// M,N multiples of 128; K multiple of 16 (true for all uses here).
// ---------------------------------------------------------------------------
__global__ __launch_bounds__(256)
void gemm_nt(const float* __restrict__ X, const float* __restrict__ Y,
             float* __restrict__ C, int M, int N, int K,
             const float* __restrict__ bias,
             size_t sX, size_t sY, size_t sC)
{
    const int b = blockIdx.z;
    X += (size_t)b * sX;  Y += (size_t)b * sY;  C += (size_t)b * sC;

    __shared__ float Xs[16][132];
    __shared__ float Ys[16][132];

    const int tid = threadIdx.x;
    const int block_row = blockIdx.y * 128;
    const int block_col = blockIdx.x * 128;

    const int lrow = tid >> 2;           // 0..63
    const int lk4  = (tid & 3) << 2;     // 0,4,8,12

    const int trow = (tid >> 4) * 8;     // 0..120
    const int tcol = (tid & 15) * 8;

    float acc[8][8];
    #pragma unroll
    for (int i = 0; i < 8; i++)
        #pragma unroll
        for (int j = 0; j < 8; j++) acc[i][j] = 0.0f;

    for (int k0 = 0; k0 < K; k0 += 16) {
        #pragma unroll
        for (int h = 0; h < 2; h++) {
            int r = lrow + h * 64;
            float4 v = *(const float4*)&X[(size_t)(block_row + r) * K + k0 + lk4];
            Xs[lk4 + 0][r] = v.x; Xs[lk4 + 1][r] = v.y;
            Xs[lk4 + 2][r] = v.z; Xs[lk4 + 3][r] = v.w;
            float4 w = *(const float4*)&Y[(size_t)(block_col + r) * K + k0 + lk4];
            Ys[lk4 + 0][r] = w.x; Ys[lk4 + 1][r] = w.y;
            Ys[lk4 + 2][r] = w.z; Ys[lk4 + 3][r] = w.w;
        }
        __syncthreads();

        #pragma unroll
        for (int kk = 0; kk < 16; kk++) {
            float4 x0 = *(const float4*)&Xs[kk][trow];
            float4 x1 = *(const float4*)&Xs[kk][trow + 4];
            float4 y0 = *(const float4*)&Ys[kk][tcol];
            float4 y1 = *(const float4*)&Ys[kk][tcol + 4];
            float xf[8] = {x0.x, x0.y, x0.z, x0.w, x1.x, x1.y, x1.z, x1.w};
            float yf[8] = {y0.x, y0.y, y0.z, y0.w, y1.x, y1.y, y1.z, y1.w};
            #pragma unroll
            for (int i = 0; i < 8; i++)
                #pragma unroll
                for (int j = 0; j < 8; j++)
                    acc[i][j] = fmaf(xf[i], yf[j], acc[i][j]);
        }
        __syncthreads();
    }

    #pragma unroll
    for (int i = 0; i < 8; i++) {
        float* crow = &C[(size_t)(block_row + trow + i) * N + block_col + tcol];
        #pragma unroll
        for (int j = 0; j < 8; j++) {
            float v = acc[i][j];
            if (bias) v += bias[block_col + tcol + j];
            crow[j] = v;
        }
    }
}

// ---------------------------------------------------------------------------
// Row softmax with diagonal masked (logit[l] -= 1e5). One block per row.
// ---------------------------------------------------------------------------
__global__ __launch_bounds__(256)
void softmax_kernel(float* __restrict__ A)
{
    const int l = blockIdx.x;
    const int b = blockIdx.y;
    float* row = A + ((size_t)b * L_ + (size_t)l) * L_;
    const int tid = threadIdx.x;

    float v[4];
    float mx = -3.0e38f;
    #pragma unroll
    for (int i = 0; i < 4; i++) {
        int c = tid + i * 256;
        float x = row[c];
        if (c == l) x -= 1e5f;
        v[i] = x;
        mx = fmaxf(mx, x);
    }

    __shared__ float red1[8];
    __shared__ float red2[8];
    #pragma unroll
    for (int o = 16; o > 0; o >>= 1)
        mx = fmaxf(mx, __shfl_xor_sync(0xffffffffu, mx, o));
    if ((tid & 31) == 0) red1[tid >> 5] = mx;
    __syncthreads();
    mx = red1[0];
    #pragma unroll
    for (int i = 1; i < 8; i++) mx = fmaxf(mx, red1[i]);

    float s = 0.0f;
    #pragma unroll
    for (int i = 0; i < 4; i++) { v[i] = expf(v[i] - mx); s += v[i]; }
    #pragma unroll
    for (int o = 16; o > 0; o >>= 1)
        s += __shfl_xor_sync(0xffffffffu, s, o);
    if ((tid & 31) == 0) red2[tid >> 5] = s;
    __syncthreads();
    s = red2[0];
    #pragma unroll
    for (int i = 1; i < 8; i++) s += red2[i];

    const float inv = 1.0f / s;
    #pragma unroll
    for (int i = 0; i < 4; i++) {
        int c = tid + i * 256;
        row[c] = v[i] * inv;
    }
}

// ---------------------------------------------------------------------------
// Centered masked labels: B0 = (sup - colsum/total) * row_has; u1 = B0 (t=1).
// One block per batch, 1024 threads (thread = row l).
// ---------------------------------------------------------------------------
__global__ __launch_bounds__(1024)
void b0_kernel(const float* __restrict__ lab, float* __restrict__ B0,
               float* __restrict__ u1)
{
    const int b = blockIdx.x;
    const int l = threadIdx.x;
    __shared__ float s_col[N_];
    __shared__ float s_total;

    const float* supb = lab + (size_t)b * L_ * N_;
    const float* sup  = supb + (size_t)l * N_;

    float rs = 0.0f;
    #pragma unroll
    for (int n = 0; n < N_; n++) rs += sup[n];
    const float rh = (rs > 0.5f) ? 1.0f : 0.0f;

    if (l == 0) s_total = 0.0f;
    __syncthreads();

    float t = rh;
    #pragma unroll
    for (int o = 16; o > 0; o >>= 1) t += __shfl_xor_sync(0xffffffffu, t, o);
    if ((l & 31) == 0) atomicAdd(&s_total, t);

    if (l < N_) {
        float cs = 0.0f;
        for (int r = 0; r < L_; r++) cs += supb[(size_t)r * N_ + l];
        s_col[l] = cs;
    }
    __syncthreads();

    const float inv_total = 1.0f / s_total;
    #pragma unroll
    for (int n = 0; n < N_; n++) {
        float v = (sup[n] - s_col[n] * inv_total) * rh;
        size_t off = ((size_t)b * L_ + l) * N_ + n;
        B0[off] = v;
        u1[off] = v;    // d == 1 in fp32: u(t=1) = d*B0 = B0
    }
}

// ---------------------------------------------------------------------------
// One power-iteration step: u_out[l,n] = sum_m A[m,l]*u_in[m,n] + B0[l,n]
// (+ predict at t==3).  A read row-major along m (the K dim) => coalesced.
// 64(l) x 64(n) tiles, BK=16, 256 threads, 4x4 per thread. Grid (16,1,8).
// ---------------------------------------------------------------------------
__global__ __launch_bounds__(256)
void iter_kernel(const float* __restrict__ A, const float* __restrict__ u_in,
                 const float* __restrict__ B0, const float* __restrict__ pred,
                 float* __restrict__ u_out)
{
    const int b = blockIdx.z;
    const int lblock = blockIdx.x * 64;
    const float* Ab = A    + (size_t)b * L_ * L_;
    const float* ub = u_in + (size_t)b * L_ * N_;

    __shared__ float Xs[16][68];   // A tile [k(m)][l]
    __shared__ float Us[16][68];   // u tile [k(m)][n]

    const int tid  = threadIdx.x;
    const int trow = (tid >> 4) * 4;   // l offset within tile (0..60)
    const int tcol = (tid & 15) * 4;   // n offset (0..60)

    const int lk  = tid >> 4;          // 0..15  (k row for loads)
    const int lc4 = (tid & 15) << 2;   // 0..60  (col*4)

    float acc[4][4];
    #pragma unroll
    for (int i = 0; i < 4; i++)
        #pragma unroll
        for (int j = 0; j < 4; j++) acc[i][j] = 0.0f;

    for (int k0 = 0; k0 < L_; k0 += 16) {
        float4 va = *(const float4*)&Ab[(size_t)(k0 + lk) * L_ + lblock + lc4];
        *(float4*)&Xs[lk][lc4] = va;
        float4 vu = *(const float4*)&ub[(size_t)(k0 + lk) * N_ + lc4];
        *(float4*)&Us[lk][lc4] = vu;
        __syncthreads();

        #pragma unroll
        for (int kk = 0; kk < 16; kk++) {
            float4 x = *(const float4*)&Xs[kk][trow];
            float4 y = *(const float4*)&Us[kk][tcol];
            float xf[4] = {x.x, x.y, x.z, x.w};
            float yf[4] = {y.x, y.y, y.z, y.w};
            #pragma unroll
            for (int i = 0; i < 4; i++)
                #pragma unroll
                for (int j = 0; j < 4; j++)
                    acc[i][j] = fmaf(xf[i], yf[j], acc[i][j]);
        }
        __syncthreads();
    }

    #pragma unroll
    for (int i = 0; i < 4; i++) {
        int l = lblock + trow + i;
        size_t base = ((size_t)b * L_ + l) * N_ + tcol;
        #pragma unroll
        for (int j = 0; j < 4; j++) {
            float v = acc[i][j] + B0[base + j];   // d == 1
            if (pred) v += pred[base + j];
            u_out[base + j] = v;
        }
    }
}

// ---------------------------------------------------------------------------
extern "C" void kernel_launch(void* const* d_in, const int* in_sizes, int n_in,
                              void* d_out, int out_size)
{
    const float* samples = (const float*)d_in[0];  // [8,1024,3072]
    const float* label   = (const float*)d_in[1];  // [8,1024,64]
    const float* predict = (const float*)d_in[2];  // [8,1024,64]
    const float* W       = (const float*)d_in[3];  // [1024,3072]
    const float* bproj   = (const float*)d_in[4];  // [1024]
    float* out = (float*)d_out;                    // [8,1024,64]

    float *s, *A, *B0, *u1, *u2;
    cudaGetSymbolAddress((void**)&s,  g_s);
    cudaGetSymbolAddress((void**)&A,  g_A);
    cudaGetSymbolAddress((void**)&B0, g_B0);
    cudaGetSymbolAddress((void**)&u1, g_u1);
    cudaGetSymbolAddress((void**)&u2, g_u2);

    const size_t LH = (size_t)L_ * H_;
    const size_t LL = (size_t)L_ * L_;

    // s = samples @ W^T + b_proj   (M=8192, N=1024, K=3072)
    gemm_nt<<<dim3(H_ / 128, (B_ * L_) / 128, 1), 256>>>(
        samples, W, s, B_ * L_, H_, K3_, bproj, 0, 0, 0);

    // graph[b] = s[b] @ s[b]^T   (per-batch 1024x1024x1024)
    gemm_nt<<<dim3(L_ / 128, L_ / 128, B_), 256>>>(
        s, s, A, L_, L_, H_, nullptr, LH, LH, LL);

    // A = softmax(graph - 1e5*I) per row
    softmax_kernel<<<dim3(L_, B_), 256>>>(A);

    // B0 + u(t=1)
    b0_kernel<<<B_, 1024>>>(label, B0, u1);

    // t=2..6: u = A^T u + B0 (+ predict at t==3)
    dim3 ig(L_ / 64, 1, B_);
    iter_kernel<<<ig, 256>>>(A, u1, B0, nullptr,  u2);  // t=2
    iter_kernel<<<ig, 256>>>(A, u2, B0, predict,  u1);  // t=3
    iter_kernel<<<ig, 256>>>(A, u1, B0, nullptr,  u2);  // t=4
    iter_kernel<<<ig, 256>>>(A, u2, B0, nullptr,  u1);  // t=5
    iter_kernel<<<ig, 256>>>(A, u1, B0, nullptr,  out); // t=6
}

// round 5
// speedup vs baseline: 2.3749x; 2.3749x over previous
#include <cuda_runtime.h>
#include <cuda_bf16.h>
#include <cstddef>
#include <cstdint>

#define B_  8
#define L_  1024
#define H_  1024
#define K3_ 3072
#define N_  64

// ---------------------------------------------------------------------------
// Static scratch (no allocations allowed)
// ---------------------------------------------------------------------------
__device__ __align__(256) __nv_bfloat16 g_smp_hi[(size_t)B_ * L_ * K3_];
__device__ __align__(256) __nv_bfloat16 g_smp_lo[(size_t)B_ * L_ * K3_];
__device__ __align__(256) __nv_bfloat16 g_W_hi [(size_t)H_ * K3_];
__device__ __align__(256) __nv_bfloat16 g_W_lo [(size_t)H_ * K3_];
__device__ __align__(256) __nv_bfloat16 g_s_hi [(size_t)B_ * L_ * H_];
__device__ __align__(256) __nv_bfloat16 g_s_lo [(size_t)B_ * L_ * H_];
__device__ __align__(256) float g_A [(size_t)B_ * L_ * L_];
__device__ __align__(256) float g_B0[(size_t)B_ * L_ * N_];
__device__ __align__(256) float g_u1[(size_t)B_ * L_ * N_];
__device__ __align__(256) float g_u2[(size_t)B_ * L_ * N_];

// ---------------------------------------------------------------------------
// PTX helpers (baseline-PTX only: cp.async / ldmatrix / mma.sync)
// ---------------------------------------------------------------------------
__device__ __forceinline__ uint32_t smem_u32(const void* p) {
    uint32_t a;
    asm("{ .reg .u64 t; cvta.to.shared.u64 t, %1; cvt.u32.u64 %0, t; }" : "=r"(a) : "l"(p));
    return a;
}

__device__ __forceinline__ void cp16(uint32_t saddr, const void* g) {
    asm volatile("cp.async.cg.shared.global [%0], [%1], 16;" :: "r"(saddr), "l"(g) : "memory");
}

__device__ __forceinline__ void ldsm4(uint32_t addr, uint32_t& r0, uint32_t& r1,
                                      uint32_t& r2, uint32_t& r3) {
    asm volatile("ldmatrix.sync.aligned.m8n8.x4.shared.b16 {%0,%1,%2,%3}, [%4];"
                 : "=r"(r0), "=r"(r1), "=r"(r2), "=r"(r3) : "r"(addr));
}

__device__ __forceinline__ void mma16816(float* c, const uint32_t* a, const uint32_t* b) {
    asm volatile(
        "mma.sync.aligned.m16n8k16.row.col.f32.bf16.bf16.f32 "
        "{%0,%1,%2,%3}, {%4,%5,%6,%7}, {%8,%9}, {%0,%1,%2,%3};"
        : "+f"(c[0]), "+f"(c[1]), "+f"(c[2]), "+f"(c[3])
        : "r"(a[0]), "r"(a[1]), "r"(a[2]), "r"(a[3]), "r"(b[0]), "r"(b[1]));
}

// ---------------------------------------------------------------------------
// fp32 -> bf16 hi/lo split (elementwise, float4 vectorized)
// ---------------------------------------------------------------------------
__global__ __launch_bounds__(256)
void split_kernel(const float* __restrict__ x, __nv_bfloat16* __restrict__ hi,
                  __nv_bfloat16* __restrict__ lo, int n4)
{
    int i = blockIdx.x * blockDim.x + threadIdx.x;
    if (i >= n4) return;
    float4 v = ((const float4*)x)[i];
    __nv_bfloat16 h0 = __float2bfloat16(v.x), h1 = __float2bfloat16(v.y);
    __nv_bfloat16 h2 = __float2bfloat16(v.z), h3 = __float2bfloat16(v.w);
    float r0 = v.x - __bfloat162float(h0);
    float r1 = v.y - __bfloat162float(h1);
    float r2 = v.z - __bfloat162float(h2);
    float r3 = v.w - __bfloat162float(h3);
    uint2 hv, lv;
    hv.x = (uint32_t)__bfloat16_as_ushort(h0) | ((uint32_t)__bfloat16_as_ushort(h1) << 16);
    hv.y = (uint32_t)__bfloat16_as_ushort(h2) | ((uint32_t)__bfloat16_as_ushort(h3) << 16);
    __nv_bfloat162 l01 = __floats2bfloat162_rn(r0, r1);
    __nv_bfloat162 l23 = __floats2bfloat162_rn(r2, r3);
    lv.x = *reinterpret_cast<uint32_t*>(&l01);
    lv.y = *reinterpret_cast<uint32_t*>(&l23);
    ((uint2*)hi)[i] = hv;
    ((uint2*)lo)[i] = lv;
}

// ---------------------------------------------------------------------------
// NT GEMM via mma.sync bf16 split: C[m,n] = sum_k X[m,k]*Y[n,k].
// Block 128x128, KC=64 stage (SW128-swizzled), double-buffered cp.async.
// 8 warps (2M x 4N), warp tile 64x32, m16n8k16 atoms, 3 products (hh,hl,lh).
// EPI=0: emit bf16 hi/lo of (acc+bias).  EPI=1: emit fp32.
// ---------------------------------------------------------------------------
#define TM 128
#define TN 128
#define KC 64
#define OFF_ALO 16384
#define OFF_BHI 32768
#define OFF_BLO 49152
#define STG     65536
#define GEMM_SMEM (2 * STG)

__device__ __forceinline__ void stage_tile(uint32_t sdst, const __nv_bfloat16* __restrict__ g,
                                           size_t row0, int ldk, int k0, int tid)
{
    #pragma unroll
    for (int i = 0; i < 4; i++) {
        int idx = tid + i * 256;
        int r = idx >> 3, c = idx & 7;
        const void* gp = g + (row0 + (size_t)r) * (size_t)ldk + k0 + c * 8;
        uint32_t off = (uint32_t)(r * 128 + (((c ^ (r & 7))) << 4));
        cp16(sdst + off, gp);
    }
}

template<int EPI>
__global__ __launch_bounds__(256)
void gemm_mma(const __nv_bfloat16* __restrict__ Ahi, const __nv_bfloat16* __restrict__ Alo,
              const __nv_bfloat16* __restrict__ Bhi, const __nv_bfloat16* __restrict__ Blo,
              int K, const float* __restrict__ bias,
              float* __restrict__ Cf, __nv_bfloat16* __restrict__ Chi,
              __nv_bfloat16* __restrict__ Clo,
              int ldc, size_t sA, size_t sB, size_t sC)
{
    extern __shared__ char smem[];
    const uint32_t sb = smem_u32(smem);
    const int tid = threadIdx.x;
    const int bz  = blockIdx.z;
    Ahi += (size_t)bz * sA;  Alo += (size_t)bz * sA;
    Bhi += (size_t)bz * sB;  Blo += (size_t)bz * sB;
    if (EPI == 0) { Chi += (size_t)bz * sC; Clo += (size_t)bz * sC; }
    else          { Cf  += (size_t)bz * sC; }

    const size_t row0 = (size_t)blockIdx.y * TM;
    const size_t col0 = (size_t)blockIdx.x * TN;

    const int lane = tid & 31, warp = tid >> 5;
    const int wm = warp >> 2, wn = warp & 3;

    float acc[4][4][4];
    #pragma unroll
    for (int i = 0; i < 4; i++)
        #pragma unroll
        for (int j = 0; j < 4; j++)
            #pragma unroll
            for (int q = 0; q < 4; q++) acc[i][j][q] = 0.0f;

    // prologue: stage 0 -> buf 0
    stage_tile(sb + 0,       Ahi, row0, K, 0, tid);
    stage_tile(sb + OFF_ALO, Alo, row0, K, 0, tid);
    stage_tile(sb + OFF_BHI, Bhi, col0, K, 0, tid);
    stage_tile(sb + OFF_BLO, Blo, col0, K, 0, tid);
    asm volatile("cp.async.commit_group;" ::: "memory");

    // ldmatrix per-thread address components (swizzle: chunk ^ (row&7), row&7 == lane&7)
    const uint32_t aRowOff = (uint32_t)((wm * 64 + (lane & 15)) * 128);
    const uint32_t bRowOff = (uint32_t)((wn * 32 + ((lane >> 4) << 3) + (lane & 7)) * 128);
    const uint32_t a_cb = (uint32_t)(lane >> 4);        // A chunk add: 0/1
    const uint32_t b_cb = (uint32_t)((lane >> 3) & 1);  // B chunk add: 0/1
    const uint32_t swz  = (uint32_t)(lane & 7);

    const int NS = K / KC;
    for (int st = 0; st < NS; st++) {
        const uint32_t sbuf = sb + (uint32_t)(st & 1) * STG;
        if (st + 1 < NS) {
            const uint32_t nbuf = sb + (uint32_t)((st + 1) & 1) * STG;
            const int k0 = (st + 1) * KC;
            stage_tile(nbuf + 0,       Ahi, row0, K, k0, tid);
            stage_tile(nbuf + OFF_ALO, Alo, row0, K, k0, tid);
            stage_tile(nbuf + OFF_BHI, Bhi, col0, K, k0, tid);
            stage_tile(nbuf + OFF_BLO, Blo, col0, K, k0, tid);
            asm volatile("cp.async.commit_group;" ::: "memory");
            asm volatile("cp.async.wait_group 1;" ::: "memory");
        } else {
            asm volatile("cp.async.wait_group 0;" ::: "memory");
        }
        __syncthreads();

        #pragma unroll
        for (int ks = 0; ks < 4; ks++) {
            const uint32_t aCol = (((uint32_t)(ks * 2) + a_cb) ^ swz) << 4;
            const uint32_t bCol = (((uint32_t)(ks * 2) + b_cb) ^ swz) << 4;

            uint32_t ah[4][4], al[4][4];
            #pragma unroll
            for (int am = 0; am < 4; am++) {
                ldsm4(sbuf + aRowOff + am * 2048 + aCol,
                      ah[am][0], ah[am][1], ah[am][2], ah[am][3]);
                ldsm4(sbuf + OFF_ALO + aRowOff + am * 2048 + aCol,
                      al[am][0], al[am][1], al[am][2], al[am][3]);
            }
            uint32_t bh[4][2], bl[4][2];
            #pragma unroll
            for (int p = 0; p < 2; p++) {
                uint32_t r0, r1, r2, r3;
                ldsm4(sbuf + OFF_BHI + bRowOff + p * 2048 + bCol, r0, r1, r2, r3);
                bh[2 * p][0] = r0; bh[2 * p][1] = r1;
                bh[2 * p + 1][0] = r2; bh[2 * p + 1][1] = r3;
                ldsm4(sbuf + OFF_BLO + bRowOff + p * 2048 + bCol, r0, r1, r2, r3);
                bl[2 * p][0] = r0; bl[2 * p][1] = r1;
                bl[2 * p + 1][0] = r2; bl[2 * p + 1][1] = r3;
            }
            #pragma unroll
            for (int am = 0; am < 4; am++)
                #pragma unroll
                for (int an = 0; an < 4; an++) {
                    mma16816(acc[am][an], ah[am], bh[an]);
                    mma16816(acc[am][an], ah[am], bl[an]);
                    mma16816(acc[am][an], al[am], bh[an]);
                }
        }
        __syncthreads();
    }

    // epilogue: direct stores (each pair = 1 fully-used 32B sector per 4 lanes)
    const int re = (int)row0 + wm * 64 + (lane >> 2);
    const int ce = (int)col0 + wn * 32 + (lane & 3) * 2;
    #pragma unroll
    for (int am = 0; am < 4; am++) {
        #pragma unroll
        for (int an = 0; an < 4; an++) {
            const int r = re + am * 16;
            const int c = ce + an * 8;
            float v0 = acc[am][an][0], v1 = acc[am][an][1];
            float v2 = acc[am][an][2], v3 = acc[am][an][3];
            if (EPI == 1) {
                *(float2*)&Cf[(size_t)r * ldc + c]       = make_float2(v0, v1);
                *(float2*)&Cf[(size_t)(r + 8) * ldc + c] = make_float2(v2, v3);
            } else {
                const float bb0 = bias[c], bb1 = bias[c + 1];
                v0 += bb0; v1 += bb1; v2 += bb0; v3 += bb1;
                __nv_bfloat16 h0 = __float2bfloat16(v0), h1 = __float2bfloat16(v1);
                __nv_bfloat16 h2 = __float2bfloat16(v2), h3 = __float2bfloat16(v3);
                float l0 = v0 - __bfloat162float(h0);
                float l1 = v1 - __bfloat162float(h1);
                float l2 = v2 - __bfloat162float(h2);
                float l3 = v3 - __bfloat162float(h3);
                uint32_t hp0 = (uint32_t)__bfloat16_as_ushort(h0) |
                               ((uint32_t)__bfloat16_as_ushort(h1) << 16);
                uint32_t hp1 = (uint32_t)__bfloat16_as_ushort(h2) |
                               ((uint32_t)__bfloat16_as_ushort(h3) << 16);
                __nv_bfloat162 lp0 = __floats2bfloat162_rn(l0, l1);
                __nv_bfloat162 lp1 = __floats2bfloat162_rn(l2, l3);
                *(uint32_t*)&Chi[(size_t)r * ldc + c]       = hp0;
                *(uint32_t*)&Chi[(size_t)(r + 8) * ldc + c] = hp1;
                *(uint32_t*)&Clo[(size_t)r * ldc + c]       = *reinterpret_cast<uint32_t*>(&lp0);
                *(uint32_t*)&Clo[(size_t)(r + 8) * ldc + c] = *reinterpret_cast<uint32_t*>(&lp1);
            }
        }
    }
}

// ---------------------------------------------------------------------------
// Row softmax with diagonal masked (logit[l] -= 1e5). One block per row.
// ---------------------------------------------------------------------------
__global__ __launch_bounds__(256)
void softmax_kernel(float* __restrict__ A)
{
    const int l = blockIdx.x;
    const int b = blockIdx.y;
    float* row = A + ((size_t)b * L_ + (size_t)l) * L_;
    const int tid = threadIdx.x;

    float v[4];
    float mx = -3.0e38f;
    #pragma unroll
    for (int i = 0; i < 4; i++) {
        int c = tid + i * 256;
        float x = row[c];
        if (c == l) x -= 1e5f;
        v[i] = x;
        mx = fmaxf(mx, x);
    }

    __shared__ float red1[8];
    __shared__ float red2[8];
    #pragma unroll
    for (int o = 16; o > 0; o >>= 1)
        mx = fmaxf(mx, __shfl_xor_sync(0xffffffffu, mx, o));
    if ((tid & 31) == 0) red1[tid >> 5] = mx;
    __syncthreads();
    mx = red1[0];
    #pragma unroll
    for (int i = 1; i < 8; i++) mx = fmaxf(mx, red1[i]);

    float s = 0.0f;
    #pragma unroll
    for (int i = 0; i < 4; i++) { v[i] = __expf(v[i] - mx); s += v[i]; }
    #pragma unroll
    for (int o = 16; o > 0; o >>= 1)
        s += __shfl_xor_sync(0xffffffffu, s, o);
    if ((tid & 31) == 0) red2[tid >> 5] = s;
    __syncthreads();
    s = red2[0];
    #pragma unroll
    for (int i = 1; i < 8; i++) s += red2[i];

    const float inv = 1.0f / s;
    #pragma unroll
    for (int i = 0; i < 4; i++) {
        int c = tid + i * 256;
        row[c] = v[i] * inv;
    }
}

// ---------------------------------------------------------------------------
// B0 = (sup - colsum/total) * row_has; u1 = B0.  Fully coalesced.
// ---------------------------------------------------------------------------
__global__ __launch_bounds__(1024)
void b0_kernel(const float* __restrict__ lab, float* __restrict__ B0,
               float* __restrict__ u1)
{
    const int b = blockIdx.x;
    const int t = threadIdx.x;
    const float* supb = lab + (size_t)b * L_ * N_;

    __shared__ float colp[16][64];
    __shared__ float s_col[64];
    __shared__ float s_rh[L_];
    __shared__ float s_tot;

    if (t == 0) s_tot = 0.0f;

    {
        const int c = t & 63, g = t >> 6;
        float cp = 0.0f;
        #pragma unroll 4
        for (int i = 0; i < 64; i++)
            cp += supb[(size_t)(i * 16 + g) * N_ + c];
        colp[g][c] = cp;
    }
    {
        const int w = t >> 5, lane = t & 31;
        for (int r = w; r < L_; r += 32) {
            float v = supb[(size_t)r * N_ + lane] + supb[(size_t)r * N_ + 32 + lane];
            #pragma unroll
            for (int o = 16; o > 0; o >>= 1) v += __shfl_xor_sync(0xffffffffu, v, o);
            if (lane == 0) s_rh[r] = (v > 0.5f) ? 1.0f : 0.0f;
        }
    }
    __syncthreads();
    if (t < 64) {
        float s = 0.0f;
        #pragma unroll
        for (int j = 0; j < 16; j++) s += colp[j][t];
        s_col[t] = s;
    }
    {
        float v = s_rh[t];
        #pragma unroll
        for (int o = 16; o > 0; o >>= 1) v += __shfl_xor_sync(0xffffffffu, v, o);
        if ((t & 31) == 0) atomicAdd(&s_tot, v);
    }
    __syncthreads();

    const float inv = 1.0f / s_tot;
    const size_t boff = (size_t)b * L_ * N_;
    #pragma unroll 4
    for (int i = 0; i < 64; i++) {
        const int idx = t + i * 1024;
        const int r = idx >> 6, n = idx & 63;
        float v = (supb[idx] - s_col[n] * inv) * s_rh[r];
        B0[boff + idx] = v;
        u1[boff + idx] = v;
    }
}

// ---------------------------------------------------------------------------
// Power-iteration step: u_out[l,n] = sum_m A[m,l]*u_in[m,n] + B0[l,n] (+pred)
// ---------------------------------------------------------------------------
__global__ __launch_bounds__(256)
void iter_kernel(const float* __restrict__ A, const float* __restrict__ u_in,
                 const float* __restrict__ B0, const float* __restrict__ pred,
                 float* __restrict__ u_out)
{
    const int b = blockIdx.z;
    const int lblock = blockIdx.x * 64;
    const float* Ab = A    + (size_t)b * L_ * L_;
    const float* ub = u_in + (size_t)b * L_ * N_;

    __shared__ float Xs[16][68];
    __shared__ float Us[16][68];

    const int tid  = threadIdx.x;
    const int trow = (tid >> 4) * 4;
    const int tcol = (tid & 15) * 4;
    const int lk   = tid >> 4;
    const int lc4  = (tid & 15) << 2;

    float acc[4][4];
    #pragma unroll
    for (int i = 0; i < 4; i++)
        #pragma unroll
        for (int j = 0; j < 4; j++) acc[i][j] = 0.0f;

    for (int k0 = 0; k0 < L_; k0 += 16) {
        float4 va = *(const float4*)&Ab[(size_t)(k0 + lk) * L_ + lblock + lc4];
        *(float4*)&Xs[lk][lc4] = va;
        float4 vu = *(const float4*)&ub[(size_t)(k0 + lk) * N_ + lc4];
        *(float4*)&Us[lk][lc4] = vu;
        __syncthreads();

        #pragma unroll
        for (int kk = 0; kk < 16; kk++) {
            float4 x = *(const float4*)&Xs[kk][trow];
            float4 y = *(const float4*)&Us[kk][tcol];
            float xf[4] = {x.x, x.y, x.z, x.w};
            float yf[4] = {y.x, y.y, y.z, y.w};
            #pragma unroll
            for (int i = 0; i < 4; i++)
                #pragma unroll
                for (int j = 0; j < 4; j++)
                    acc[i][j] = fmaf(xf[i], yf[j], acc[i][j]);
        }
        __syncthreads();
    }

    #pragma unroll
    for (int i = 0; i < 4; i++) {
        int l = lblock + trow + i;
        size_t base = ((size_t)b * L_ + l) * N_ + tcol;
        #pragma unroll
        for (int j = 0; j < 4; j++) {
            float v = acc[i][j] + B0[base + j];
            if (pred) v += pred[base + j];
            u_out[base + j] = v;
        }
    }
}

// ---------------------------------------------------------------------------
extern "C" void kernel_launch(void* const* d_in, const int* in_sizes, int n_in,
                              void* d_out, int out_size)
{
    const float* samples = (const float*)d_in[0];  // [8,1024,3072]
    const float* label   = (const float*)d_in[1];  // [8,1024,64]
    const float* predict = (const float*)d_in[2];  // [8,1024,64]
    const float* W       = (const float*)d_in[3];  // [1024,3072]
    const float* bproj   = (const float*)d_in[4];  // [1024]
    float* out = (float*)d_out;                    // [8,1024,64]

    __nv_bfloat16 *smph, *smpl, *Wh, *Wl, *sh, *sl;
    float *A, *B0, *u1, *u2;
    cudaGetSymbolAddress((void**)&smph, g_smp_hi);
    cudaGetSymbolAddress((void**)&smpl, g_smp_lo);
    cudaGetSymbolAddress((void**)&Wh,   g_W_hi);
    cudaGetSymbolAddress((void**)&Wl,   g_W_lo);
    cudaGetSymbolAddress((void**)&sh,   g_s_hi);
    cudaGetSymbolAddress((void**)&sl,   g_s_lo);
    cudaGetSymbolAddress((void**)&A,    g_A);
    cudaGetSymbolAddress((void**)&B0,   g_B0);
    cudaGetSymbolAddress((void**)&u1,   g_u1);
    cudaGetSymbolAddress((void**)&u2,   g_u2);

    cudaFuncSetAttribute(gemm_mma<0>, cudaFuncAttributeMaxDynamicSharedMemorySize, GEMM_SMEM);
    cudaFuncSetAttribute(gemm_mma<1>, cudaFuncAttributeMaxDynamicSharedMemorySize, GEMM_SMEM);

    const size_t LH = (size_t)L_ * H_;
    const size_t LL = (size_t)L_ * L_;

    // split fp32 -> bf16 hi/lo
    {
        int n4 = (B_ * L_ * K3_) / 4;
        split_kernel<<<(n4 + 255) / 256, 256>>>(samples, smph, smpl, n4);
        int w4 = (H_ * K3_) / 4;
        split_kernel<<<(w4 + 255) / 256, 256>>>(W, Wh, Wl, w4);
    }

    // s = samples @ W^T + b_proj  -> bf16 hi/lo
    gemm_mma<0><<<dim3(H_ / TN, (B_ * L_) / TM, 1), 256, GEMM_SMEM>>>(
        smph, smpl, Wh, Wl, K3_, bproj, nullptr, sh, sl, H_, 0, 0, 0);

    // graph[b] = s[b] @ s[b]^T  -> fp32
    gemm_mma<1><<<dim3(L_ / TN, L_ / TM, B_), 256, GEMM_SMEM>>>(
        sh, sl, sh, sl, H_, nullptr, A, nullptr, nullptr, L_, LH, LH, LL);

    // A = softmax(graph - 1e5*I) per row
    softmax_kernel<<<dim3(L_, B_), 256>>>(A);

    // B0 + u(t=1)
    b0_kernel<<<B_, 1024>>>(label, B0, u1);

    // t=2..6: u = A^T u + B0 (+ predict at t==3)
    dim3 ig(L_ / 64, 1, B_);
    iter_kernel<<<ig, 256>>>(A, u1, B0, nullptr,  u2);  // t=2
    iter_kernel<<<ig, 256>>>(A, u2, B0, predict,  u1);  // t=3
    iter_kernel<<<ig, 256>>>(A, u1, B0, nullptr,  u2);  // t=4
    iter_kernel<<<ig, 256>>>(A, u2, B0, nullptr,  u1);  // t=5
    iter_kernel<<<ig, 256>>>(A, u1, B0, nullptr,  out); // t=6
}

// round 6
// speedup vs baseline: 2.5232x; 1.0624x over previous
#include <cuda_runtime.h>
#include <cuda_bf16.h>
#include <cstddef>
#include <cstdint>

#define B_  8
#define L_  1024
#define H_  1024
#define K3_ 3072
#define N_  64

// ---------------------------------------------------------------------------
// Static scratch (no allocations allowed)
// ---------------------------------------------------------------------------
__device__ __align__(256) __nv_bfloat16 g_smp_hi[(size_t)B_ * L_ * K3_];
__device__ __align__(256) __nv_bfloat16 g_smp_lo[(size_t)B_ * L_ * K3_];
__device__ __align__(256) __nv_bfloat16 g_W_hi [(size_t)H_ * K3_];
__device__ __align__(256) __nv_bfloat16 g_W_lo [(size_t)H_ * K3_];
__device__ __align__(256) __nv_bfloat16 g_s_hi [(size_t)B_ * L_ * H_];
__device__ __align__(256) __nv_bfloat16 g_s_lo [(size_t)B_ * L_ * H_];
__device__ __align__(256) float g_A [(size_t)B_ * L_ * L_];
__device__ __align__(256) float g_B0[(size_t)B_ * L_ * N_];
__device__ __align__(256) float g_u1[(size_t)B_ * L_ * N_];
__device__ __align__(256) float g_u2[(size_t)B_ * L_ * N_];

// ---------------------------------------------------------------------------
// PTX helpers (baseline-PTX only: cp.async / ldmatrix / mma.sync)
// ---------------------------------------------------------------------------
__device__ __forceinline__ uint32_t smem_u32(const void* p) {
    uint32_t a;
    asm("{ .reg .u64 t; cvta.to.shared.u64 t, %1; cvt.u32.u64 %0, t; }" : "=r"(a) : "l"(p));
    return a;
}

__device__ __forceinline__ void cp16(uint32_t saddr, const void* g) {
    asm volatile("cp.async.cg.shared.global [%0], [%1], 16;" :: "r"(saddr), "l"(g) : "memory");
}

__device__ __forceinline__ void ldsm4(uint32_t addr, uint32_t& r0, uint32_t& r1,
                                      uint32_t& r2, uint32_t& r3) {
    asm volatile("ldmatrix.sync.aligned.m8n8.x4.shared.b16 {%0,%1,%2,%3}, [%4];"
                 : "=r"(r0), "=r"(r1), "=r"(r2), "=r"(r3) : "r"(addr));
}

__device__ __forceinline__ void mma16816(float* c, const uint32_t* a, const uint32_t* b) {
    asm volatile(
        "mma.sync.aligned.m16n8k16.row.col.f32.bf16.bf16.f32 "
        "{%0,%1,%2,%3}, {%4,%5,%6,%7}, {%8,%9}, {%0,%1,%2,%3};"
        : "+f"(c[0]), "+f"(c[1]), "+f"(c[2]), "+f"(c[3])
        : "r"(a[0]), "r"(a[1]), "r"(a[2]), "r"(a[3]), "r"(b[0]), "r"(b[1]));
}

// ---------------------------------------------------------------------------
// fp32 -> bf16 hi/lo split (elementwise, float4 vectorized)
// ---------------------------------------------------------------------------
__global__ __launch_bounds__(256)
void split_kernel(const float* __restrict__ x, __nv_bfloat16* __restrict__ hi,
                  __nv_bfloat16* __restrict__ lo, int n4)
{
    int i = blockIdx.x * blockDim.x + threadIdx.x;
    if (i >= n4) return;
    float4 v = ((const float4*)x)[i];
    __nv_bfloat16 h0 = __float2bfloat16(v.x), h1 = __float2bfloat16(v.y);
    __nv_bfloat16 h2 = __float2bfloat16(v.z), h3 = __float2bfloat16(v.w);
    float r0 = v.x - __bfloat162float(h0);
    float r1 = v.y - __bfloat162float(h1);
    float r2 = v.z - __bfloat162float(h2);
    float r3 = v.w - __bfloat162float(h3);
    uint2 hv, lv;
    hv.x = (uint32_t)__bfloat16_as_ushort(h0) | ((uint32_t)__bfloat16_as_ushort(h1) << 16);
    hv.y = (uint32_t)__bfloat16_as_ushort(h2) | ((uint32_t)__bfloat16_as_ushort(h3) << 16);
    __nv_bfloat162 l01 = __floats2bfloat162_rn(r0, r1);
    __nv_bfloat162 l23 = __floats2bfloat162_rn(r2, r3);
    lv.x = *reinterpret_cast<uint32_t*>(&l01);
    lv.y = *reinterpret_cast<uint32_t*>(&l23);
    ((uint2*)hi)[i] = hv;
    ((uint2*)lo)[i] = lv;
}

// ---------------------------------------------------------------------------
// NT GEMM via mma.sync bf16 split: C[m,n] = sum_k X[m,k]*Y[n,k].
// Block 128x128, KC=32 stages, 3-stage cp.async ring (96 KB) -> 2 CTAs/SM.
// 8 warps (2M x 4N), warp tile 64x32, m16n8k16 atoms, 3 products (hh,hl,lh).
// Paired-row swizzle (64B rows): line = r>>1, chunk = ((r&1)*4+c) ^ (line&7).
// EPI=0: emit bf16 hi/lo of (acc+bias).  EPI=1: emit fp32.
// ---------------------------------------------------------------------------
#define TM 128
#define TN 128
#define KC 32
#define OFF_ALO 8192
#define OFF_BHI 16384
#define OFF_BLO 24576
#define STG     32768
#define NSTAGE  3
#define GEMM_SMEM (NSTAGE * STG)

__device__ __forceinline__ void stage_half(uint32_t sdst, const __nv_bfloat16* __restrict__ g,
                                           size_t row0, int ldk, int k0, int tid)
{
    #pragma unroll
    for (int i = 0; i < 2; i++) {
        int idx = tid + i * 256;         // 0..511
        int r = idx >> 2, c = idx & 3;   // 128 rows x 4 chunks(16B)
        const void* gp = g + (row0 + (size_t)r) * (size_t)ldk + k0 + c * 8;
        uint32_t line = (uint32_t)(r >> 1);
        uint32_t off = line * 128 + ((((uint32_t)(r & 1) * 4 + (uint32_t)c) ^ (line & 7)) << 4);
        cp16(sdst + off, gp);
    }
}

__device__ __forceinline__ void stage_all(uint32_t sbuf,
        const __nv_bfloat16* Ahi, const __nv_bfloat16* Alo,
        const __nv_bfloat16* Bhi, const __nv_bfloat16* Blo,
        size_t row0, size_t col0, int K, int k0, int tid)
{
    stage_half(sbuf + 0,       Ahi, row0, K, k0, tid);
    stage_half(sbuf + OFF_ALO, Alo, row0, K, k0, tid);
    stage_half(sbuf + OFF_BHI, Bhi, col0, K, k0, tid);
    stage_half(sbuf + OFF_BLO, Blo, col0, K, k0, tid);
    asm volatile("cp.async.commit_group;" ::: "memory");
}

template<int EPI>
__global__ __launch_bounds__(256, 2)
void gemm_mma(const __nv_bfloat16* __restrict__ Ahi, const __nv_bfloat16* __restrict__ Alo,
              const __nv_bfloat16* __restrict__ Bhi, const __nv_bfloat16* __restrict__ Blo,
              int K, const float* __restrict__ bias,
              float* __restrict__ Cf, __nv_bfloat16* __restrict__ Chi,
              __nv_bfloat16* __restrict__ Clo,
              int ldc, size_t sA, size_t sB, size_t sC)
{
    extern __shared__ __align__(1024) char smem[];
    const uint32_t sb = smem_u32(smem);
    const int tid = threadIdx.x;
    const int bz  = blockIdx.z;
    Ahi += (size_t)bz * sA;  Alo += (size_t)bz * sA;
    Bhi += (size_t)bz * sB;  Blo += (size_t)bz * sB;
    if (EPI == 0) { Chi += (size_t)bz * sC; Clo += (size_t)bz * sC; }
    else          { Cf  += (size_t)bz * sC; }

    const size_t row0 = (size_t)blockIdx.y * TM;
    const size_t col0 = (size_t)blockIdx.x * TN;

    const int lane = tid & 31, warp = tid >> 5;
    const int wm = warp >> 2, wn = warp & 3;

    // ldmatrix per-lane address precompute (paired-row swizzle)
    // A: row = wm*64 + am*16 + (lane&15); k-chunk c = 2*ks + (lane>>4)
    const uint32_t dlA = (uint32_t)((lane & 15) >> 1);
    const uint32_t baseA = (uint32_t)(wm * 32 + dlA) * 128;        // + am*1024
    uint32_t chA[2];
    #pragma unroll
    for (int ks = 0; ks < 2; ks++)
        chA[ks] = ((((uint32_t)(lane & 1) << 2) + (uint32_t)(2 * ks + (lane >> 4))) ^ dlA) << 4;
    // B: row = wn*32 + p*16 + v, v = (lane&7)|((lane>>4)<<3); c = 2*ks + ((lane>>3)&1)
    const uint32_t vB  = (uint32_t)((lane & 7) | ((lane >> 4) << 3));
    const uint32_t dlB = vB >> 1;
    const uint32_t baseB = (uint32_t)(wn * 16 + dlB) * 128;        // + p*1024
    uint32_t chB[2];
    #pragma unroll
    for (int ks = 0; ks < 2; ks++)
        chB[ks] = ((((uint32_t)(lane & 1) << 2) + (uint32_t)(2 * ks + ((lane >> 3) & 1))) ^ dlB) << 4;

    float acc[4][4][4];
    #pragma unroll
    for (int i = 0; i < 4; i++)
        #pragma unroll
        for (int j = 0; j < 4; j++)
            #pragma unroll
            for (int q = 0; q < 4; q++) acc[i][j][q] = 0.0f;

    const int NS = K / KC;
    // prologue: stages 0 and 1
    stage_all(sb + 0 * STG, Ahi, Alo, Bhi, Blo, row0, col0, K, 0,  tid);
    stage_all(sb + 1 * STG, Ahi, Alo, Bhi, Blo, row0, col0, K, KC, tid);

    int buf = 0;
    for (int st = 0; st < NS; st++) {
        if (st + 1 < NS) asm volatile("cp.async.wait_group 1;" ::: "memory");
        else             asm volatile("cp.async.wait_group 0;" ::: "memory");
        __syncthreads();

        const uint32_t sbuf = sb + (uint32_t)buf * STG;
        #pragma unroll
        for (int ks = 0; ks < 2; ks++) {
            uint32_t ah[4][4], al[4][4];
            #pragma unroll
            for (int am = 0; am < 4; am++) {
                ldsm4(sbuf + baseA + am * 1024 + chA[ks],
                      ah[am][0], ah[am][1], ah[am][2], ah[am][3]);
                ldsm4(sbuf + OFF_ALO + baseA + am * 1024 + chA[ks],
                      al[am][0], al[am][1], al[am][2], al[am][3]);
            }
            uint32_t bh[4][2], bl[4][2];
            #pragma unroll
            for (int p = 0; p < 2; p++) {
                uint32_t r0, r1, r2, r3;
                ldsm4(sbuf + OFF_BHI + baseB + p * 1024 + chB[ks], r0, r1, r2, r3);
                bh[2 * p][0] = r0; bh[2 * p][1] = r1;
                bh[2 * p + 1][0] = r2; bh[2 * p + 1][1] = r3;
                ldsm4(sbuf + OFF_BLO + baseB + p * 1024 + chB[ks], r0, r1, r2, r3);
                bl[2 * p][0] = r0; bl[2 * p][1] = r1;
                bl[2 * p + 1][0] = r2; bl[2 * p + 1][1] = r3;
            }
            #pragma unroll
            for (int am = 0; am < 4; am++)
                #pragma unroll
                for (int an = 0; an < 4; an++) {
                    mma16816(acc[am][an], ah[am], bh[an]);
                    mma16816(acc[am][an], ah[am], bl[an]);
                    mma16816(acc[am][an], al[am], bh[an]);
                }
        }

        if (st + 2 < NS) {
            int nb = buf + 2; if (nb >= NSTAGE) nb -= NSTAGE;
            stage_all(sb + (uint32_t)nb * STG, Ahi, Alo, Bhi, Blo,
                      row0, col0, K, (st + 2) * KC, tid);
        }
        if (++buf == NSTAGE) buf = 0;
    }

    // epilogue: direct stores (8B per 4 lanes -> full 32B sectors)
    const int re = (int)row0 + wm * 64 + (lane >> 2);
    const int ce = (int)col0 + wn * 32 + (lane & 3) * 2;
    #pragma unroll
    for (int am = 0; am < 4; am++) {
        #pragma unroll
        for (int an = 0; an < 4; an++) {
            const int r = re + am * 16;
            const int c = ce + an * 8;
            float v0 = acc[am][an][0], v1 = acc[am][an][1];
            float v2 = acc[am][an][2], v3 = acc[am][an][3];
            if (EPI == 1) {
                *(float2*)&Cf[(size_t)r * ldc + c]       = make_float2(v0, v1);
                *(float2*)&Cf[(size_t)(r + 8) * ldc + c] = make_float2(v2, v3);
            } else {
                const float bb0 = bias[c], bb1 = bias[c + 1];
                v0 += bb0; v1 += bb1; v2 += bb0; v3 += bb1;
                __nv_bfloat16 h0 = __float2bfloat16(v0), h1 = __float2bfloat16(v1);
                __nv_bfloat16 h2 = __float2bfloat16(v2), h3 = __float2bfloat16(v3);
                float l0 = v0 - __bfloat162float(h0);
                float l1 = v1 - __bfloat162float(h1);
                float l2 = v2 - __bfloat162float(h2);
                float l3 = v3 - __bfloat162float(h3);
                uint32_t hp0 = (uint32_t)__bfloat16_as_ushort(h0) |
                               ((uint32_t)__bfloat16_as_ushort(h1) << 16);
                uint32_t hp1 = (uint32_t)__bfloat16_as_ushort(h2) |
                               ((uint32_t)__bfloat16_as_ushort(h3) << 16);
                __nv_bfloat162 lp0 = __floats2bfloat162_rn(l0, l1);
                __nv_bfloat162 lp1 = __floats2bfloat162_rn(l2, l3);
                *(uint32_t*)&Chi[(size_t)r * ldc + c]       = hp0;
                *(uint32_t*)&Chi[(size_t)(r + 8) * ldc + c] = hp1;
                *(uint32_t*)&Clo[(size_t)r * ldc + c]       = *reinterpret_cast<uint32_t*>(&lp0);
                *(uint32_t*)&Clo[(size_t)(r + 8) * ldc + c] = *reinterpret_cast<uint32_t*>(&lp1);
            }
        }
    }
}

// ---------------------------------------------------------------------------
// Row softmax with diagonal masked (logit[l] -= 1e5). One block per row.
// ---------------------------------------------------------------------------
__global__ __launch_bounds__(256)
void softmax_kernel(float* __restrict__ A)
{
    const int l = blockIdx.x;
    const int b = blockIdx.y;
    float* row = A + ((size_t)b * L_ + (size_t)l) * L_;
    const int tid = threadIdx.x;

    float4 v = ((const float4*)row)[tid];
    if ((l >> 2) == tid) (&v.x)[l & 3] -= 1e5f;

    float mx = fmaxf(fmaxf(v.x, v.y), fmaxf(v.z, v.w));

    __shared__ float red1[8];
    __shared__ float red2[8];
    #pragma unroll
    for (int o = 16; o > 0; o >>= 1)
        mx = fmaxf(mx, __shfl_xor_sync(0xffffffffu, mx, o));
    if ((tid & 31) == 0) red1[tid >> 5] = mx;
    __syncthreads();
    mx = red1[0];
    #pragma unroll
    for (int i = 1; i < 8; i++) mx = fmaxf(mx, red1[i]);

    v.x = __expf(v.x - mx); v.y = __expf(v.y - mx);
    v.z = __expf(v.z - mx); v.w = __expf(v.w - mx);
    float s = (v.x + v.y) + (v.z + v.w);
    #pragma unroll
    for (int o = 16; o > 0; o >>= 1)
        s += __shfl_xor_sync(0xffffffffu, s, o);
    if ((tid & 31) == 0) red2[tid >> 5] = s;
    __syncthreads();
    s = red2[0];
    #pragma unroll
    for (int i = 1; i < 8; i++) s += red2[i];

    const float inv = 1.0f / s;
    v.x *= inv; v.y *= inv; v.z *= inv; v.w *= inv;
    ((float4*)row)[tid] = v;
}

// ---------------------------------------------------------------------------
// B0 = (sup - colsum/total) * row_has; u1 = B0.  Fully coalesced.
// ---------------------------------------------------------------------------
__global__ __launch_bounds__(1024)
void b0_kernel(const float* __restrict__ lab, float* __restrict__ B0,
               float* __restrict__ u1)
{
    const int b = blockIdx.x;
    const int t = threadIdx.x;
    const float* supb = lab + (size_t)b * L_ * N_;

    __shared__ float colp[16][64];
    __shared__ float s_col[64];
    __shared__ float s_rh[L_];
    __shared__ float s_tot;

    if (t == 0) s_tot = 0.0f;

    {
        const int c = t & 63, g = t >> 6;
        float cp = 0.0f;
        #pragma unroll 4
        for (int i = 0; i < 64; i++)
            cp += supb[(size_t)(i * 16 + g) * N_ + c];
        colp[g][c] = cp;
    }
    {
        const int w = t >> 5, lane = t & 31;
        for (int r = w; r < L_; r += 32) {
            float v = supb[(size_t)r * N_ + lane] + supb[(size_t)r * N_ + 32 + lane];
            #pragma unroll
            for (int o = 16; o > 0; o >>= 1) v += __shfl_xor_sync(0xffffffffu, v, o);
            if (lane == 0) s_rh[r] = (v > 0.5f) ? 1.0f : 0.0f;
        }
    }
    __syncthreads();
    if (t < 64) {
        float s = 0.0f;
        #pragma unroll
        for (int j = 0; j < 16; j++) s += colp[j][t];
        s_col[t] = s;
    }
    {
        float v = s_rh[t];
        #pragma unroll
        for (int o = 16; o > 0; o >>= 1) v += __shfl_xor_sync(0xffffffffu, v, o);
        if ((t & 31) == 0) atomicAdd(&s_tot, v);
    }
    __syncthreads();

    const float inv = 1.0f / s_tot;
    const size_t boff = (size_t)b * L_ * N_;
    #pragma unroll 4
    for (int i = 0; i < 64; i++) {
        const int idx = t + i * 1024;
        const int r = idx >> 6, n = idx & 63;
        float v = (supb[idx] - s_col[n] * inv) * s_rh[r];
        B0[boff + idx] = v;
        u1[boff + idx] = v;
    }
}

// ---------------------------------------------------------------------------
// Power-iteration step: u_out[l,n] = sum_m A[m,l]*u_in[m,n] + B0[l,n] (+pred)
// ---------------------------------------------------------------------------
__global__ __launch_bounds__(256)
void iter_kernel(const float* __restrict__ A, const float* __restrict__ u_in,
                 const float* __restrict__ B0, const float* __restrict__ pred,
                 float* __restrict__ u_out)
{
    const int b = blockIdx.z;
    const int lblock = blockIdx.x * 64;
    const float* Ab = A    + (size_t)b * L_ * L_;
    const float* ub = u_in + (size_t)b * L_ * N_;

    __shared__ float Xs[16][68];
    __shared__ float Us[16][68];

    const int tid  = threadIdx.x;
    const int trow = (tid >> 4) * 4;
    const int tcol = (tid & 15) * 4;
    const int lk   = tid >> 4;
    const int lc4  = (tid & 15) << 2;

    float acc[4][4];
    #pragma unroll
    for (int i = 0; i < 4; i++)
        #pragma unroll
        for (int j = 0; j < 4; j++) acc[i][j] = 0.0f;

    for (int k0 = 0; k0 < L_; k0 += 16) {
        float4 va = *(const float4*)&Ab[(size_t)(k0 + lk) * L_ + lblock + lc4];
        *(float4*)&Xs[lk][lc4] = va;
        float4 vu = *(const float4*)&ub[(size_t)(k0 + lk) * N_ + lc4];
        *(float4*)&Us[lk][lc4] = vu;
        __syncthreads();

        #pragma unroll
        for (int kk = 0; kk < 16; kk++) {
            float4 x = *(const float4*)&Xs[kk][trow];
            float4 y = *(const float4*)&Us[kk][tcol];
            float xf[4] = {x.x, x.y, x.z, x.w};
            float yf[4] = {y.x, y.y, y.z, y.w};
            #pragma unroll
            for (int i = 0; i < 4; i++)
                #pragma unroll
                for (int j = 0; j < 4; j++)
                    acc[i][j] = fmaf(xf[i], yf[j], acc[i][j]);
        }
        __syncthreads();
    }

    #pragma unroll
    for (int i = 0; i < 4; i++) {
        int l = lblock + trow + i;
        size_t base = ((size_t)b * L_ + l) * N_ + tcol;
        #pragma unroll
        for (int j = 0; j < 4; j++) {
            float v = acc[i][j] + B0[base + j];
            if (pred) v += pred[base + j];
            u_out[base + j] = v;
        }
    }
}

// ---------------------------------------------------------------------------
extern "C" void kernel_launch(void* const* d_in, const int* in_sizes, int n_in,
                              void* d_out, int out_size)
{
    const float* samples = (const float*)d_in[0];  // [8,1024,3072]
    const float* label   = (const float*)d_in[1];  // [8,1024,64]
    const float* predict = (const float*)d_in[2];  // [8,1024,64]
    const float* W       = (const float*)d_in[3];  // [1024,3072]
    const float* bproj   = (const float*)d_in[4];  // [1024]
    float* out = (float*)d_out;                    // [8,1024,64]

    __nv_bfloat16 *smph, *smpl, *Wh, *Wl, *sh, *sl;
    float *A, *B0, *u1, *u2;
    cudaGetSymbolAddress((void**)&smph, g_smp_hi);
    cudaGetSymbolAddress((void**)&smpl, g_smp_lo);
    cudaGetSymbolAddress((void**)&Wh,   g_W_hi);
    cudaGetSymbolAddress((void**)&Wl,   g_W_lo);
    cudaGetSymbolAddress((void**)&sh,   g_s_hi);
    cudaGetSymbolAddress((void**)&sl,   g_s_lo);
    cudaGetSymbolAddress((void**)&A,    g_A);
    cudaGetSymbolAddress((void**)&B0,   g_B0);
    cudaGetSymbolAddress((void**)&u1,   g_u1);
    cudaGetSymbolAddress((void**)&u2,   g_u2);

    cudaFuncSetAttribute(gemm_mma<0>, cudaFuncAttributeMaxDynamicSharedMemorySize, GEMM_SMEM);
    cudaFuncSetAttribute(gemm_mma<1>, cudaFuncAttributeMaxDynamicSharedMemorySize, GEMM_SMEM);

    const size_t LH = (size_t)L_ * H_;
    const size_t LL = (size_t)L_ * L_;

    // split fp32 -> bf16 hi/lo
    {
        int n4 = (B_ * L_ * K3_) / 4;
        split_kernel<<<(n4 + 255) / 256, 256>>>(samples, smph, smpl, n4);
        int w4 = (H_ * K3_) / 4;
        split_kernel<<<(w4 + 255) / 256, 256>>>(W, Wh, Wl, w4);
    }

    // s = samples @ W^T + b_proj  -> bf16 hi/lo
    gemm_mma<0><<<dim3(H_ / TN, (B_ * L_) / TM, 1), 256, GEMM_SMEM>>>(
        smph, smpl, Wh, Wl, K3_, bproj, nullptr, sh, sl, H_, 0, 0, 0);

    // graph[b] = s[b] @ s[b]^T  -> fp32
    gemm_mma<1><<<dim3(L_ / TN, L_ / TM, B_), 256, GEMM_SMEM>>>(
        sh, sl, sh, sl, H_, nullptr, A, nullptr, nullptr, L_, LH, LH, LL);

    // A = softmax(graph - 1e5*I) per row
    softmax_kernel<<<dim3(L_, B_), 256>>>(A);

    // B0 + u(t=1)
    b0_kernel<<<B_, 1024>>>(label, B0, u1);

    // t=2..6: u = A^T u + B0 (+ predict at t==3)
    dim3 ig(L_ / 64, 1, B_);
    iter_kernel<<<ig, 256>>>(A, u1, B0, nullptr,  u2);  // t=2
    iter_kernel<<<ig, 256>>>(A, u2, B0, predict,  u1);  // t=3
    iter_kernel<<<ig, 256>>>(A, u1, B0, nullptr,  u2);  // t=4
    iter_kernel<<<ig, 256>>>(A, u2, B0, nullptr,  u1);  // t=5
    iter_kernel<<<ig, 256>>>(A, u1, B0, nullptr,  out); // t=6
}

// round 8
// speedup vs baseline: 3.0204x; 1.1970x over previous
#include <cuda_runtime.h>
#include <cuda_bf16.h>
#include <cstddef>
#include <cstdint>

#define B_  8
#define L_  1024
#define H_  1024
#define K3_ 3072
#define N_  64

// ---------------------------------------------------------------------------
// Static scratch (no allocations allowed)
// ---------------------------------------------------------------------------
__device__ __align__(256) __nv_bfloat16 g_smp_hi[(size_t)B_ * L_ * K3_];
__device__ __align__(256) __nv_bfloat16 g_smp_lo[(size_t)B_ * L_ * K3_];
__device__ __align__(256) __nv_bfloat16 g_W_hi [(size_t)H_ * K3_];
__device__ __align__(256) __nv_bfloat16 g_W_lo [(size_t)H_ * K3_];
__device__ __align__(256) __nv_bfloat16 g_s_hi [(size_t)B_ * L_ * H_];  // later: A_hi
__device__ __align__(256) __nv_bfloat16 g_s_lo [(size_t)B_ * L_ * H_];  // later: A_lo
__device__ __align__(256) float g_A [(size_t)B_ * L_ * L_];             // graph (fp32)
__device__ __align__(256) float g_B0[(size_t)B_ * L_ * N_];
__device__ __align__(256) __nv_bfloat16 g_uh1[(size_t)B_ * L_ * N_];
__device__ __align__(256) __nv_bfloat16 g_ul1[(size_t)B_ * L_ * N_];
__device__ __align__(256) __nv_bfloat16 g_uh2[(size_t)B_ * L_ * N_];
__device__ __align__(256) __nv_bfloat16 g_ul2[(size_t)B_ * L_ * N_];

// ---------------------------------------------------------------------------
// PTX helpers (baseline-PTX only: cp.async / ldmatrix / mma.sync)
// ---------------------------------------------------------------------------
__device__ __forceinline__ uint32_t smem_u32(const void* p) {
    uint32_t a;
    asm("{ .reg .u64 t; cvta.to.shared.u64 t, %1; cvt.u32.u64 %0, t; }" : "=r"(a) : "l"(p));
    return a;
}

__device__ __forceinline__ void cp16(uint32_t saddr, const void* g) {
    asm volatile("cp.async.cg.shared.global [%0], [%1], 16;" :: "r"(saddr), "l"(g) : "memory");
}

__device__ __forceinline__ void ldsm4(uint32_t addr, uint32_t& r0, uint32_t& r1,
                                      uint32_t& r2, uint32_t& r3) {
    asm volatile("ldmatrix.sync.aligned.m8n8.x4.shared.b16 {%0,%1,%2,%3}, [%4];"
                 : "=r"(r0), "=r"(r1), "=r"(r2), "=r"(r3) : "r"(addr));
}

__device__ __forceinline__ void ldsm4t(uint32_t addr, uint32_t& r0, uint32_t& r1,
                                       uint32_t& r2, uint32_t& r3) {
    asm volatile("ldmatrix.sync.aligned.m8n8.x4.trans.shared.b16 {%0,%1,%2,%3}, [%4];"
                 : "=r"(r0), "=r"(r1), "=r"(r2), "=r"(r3) : "r"(addr));
}

__device__ __forceinline__ void mma16816(float* c, const uint32_t* a, const uint32_t* b) {
    asm volatile(
        "mma.sync.aligned.m16n8k16.row.col.f32.bf16.bf16.f32 "
        "{%0,%1,%2,%3}, {%4,%5,%6,%7}, {%8,%9}, {%0,%1,%2,%3};"
        : "+f"(c[0]), "+f"(c[1]), "+f"(c[2]), "+f"(c[3])
        : "r"(a[0]), "r"(a[1]), "r"(a[2]), "r"(a[3]), "r"(b[0]), "r"(b[1]));
}

// ---------------------------------------------------------------------------
// fp32 -> bf16 hi/lo split (elementwise, float4 vectorized)
// ---------------------------------------------------------------------------
__global__ __launch_bounds__(256)
void split_kernel(const float* __restrict__ x, __nv_bfloat16* __restrict__ hi,
                  __nv_bfloat16* __restrict__ lo, int n4)
{
    int i = blockIdx.x * blockDim.x + threadIdx.x;
    if (i >= n4) return;
    float4 v = ((const float4*)x)[i];
    __nv_bfloat16 h0 = __float2bfloat16(v.x), h1 = __float2bfloat16(v.y);
    __nv_bfloat16 h2 = __float2bfloat16(v.z), h3 = __float2bfloat16(v.w);
    float r0 = v.x - __bfloat162float(h0);
    float r1 = v.y - __bfloat162float(h1);
    float r2 = v.z - __bfloat162float(h2);
    float r3 = v.w - __bfloat162float(h3);
    uint2 hv, lv;
    hv.x = (uint32_t)__bfloat16_as_ushort(h0) | ((uint32_t)__bfloat16_as_ushort(h1) << 16);
    hv.y = (uint32_t)__bfloat16_as_ushort(h2) | ((uint32_t)__bfloat16_as_ushort(h3) << 16);
    __nv_bfloat162 l01 = __floats2bfloat162_rn(r0, r1);
    __nv_bfloat162 l23 = __floats2bfloat162_rn(r2, r3);
    lv.x = *reinterpret_cast<uint32_t*>(&l01);
    lv.y = *reinterpret_cast<uint32_t*>(&l23);
    ((uint2*)hi)[i] = hv;
    ((uint2*)lo)[i] = lv;
}

// ---------------------------------------------------------------------------
// NT GEMM via mma.sync bf16 split (unchanged from R6)
// ---------------------------------------------------------------------------
#define TM 128
#define TN 128
#define KC 32
#define OFF_ALO 8192
#define OFF_BHI 16384
#define OFF_BLO 24576
#define STG     32768
#define NSTAGE  3
#define GEMM_SMEM (NSTAGE * STG)

__device__ __forceinline__ void stage_half(uint32_t sdst, const __nv_bfloat16* __restrict__ g,
                                           size_t row0, int ldk, int k0, int tid)
{
    #pragma unroll
    for (int i = 0; i < 2; i++) {
        int idx = tid + i * 256;
        int r = idx >> 2, c = idx & 3;
        const void* gp = g + (row0 + (size_t)r) * (size_t)ldk + k0 + c * 8;
        uint32_t line = (uint32_t)(r >> 1);
        uint32_t off = line * 128 + ((((uint32_t)(r & 1) * 4 + (uint32_t)c) ^ (line & 7)) << 4);
        cp16(sdst + off, gp);
    }
}

__device__ __forceinline__ void stage_all(uint32_t sbuf,
        const __nv_bfloat16* Ahi, const __nv_bfloat16* Alo,
        const __nv_bfloat16* Bhi, const __nv_bfloat16* Blo,
        size_t row0, size_t col0, int K, int k0, int tid)
{
    stage_half(sbuf + 0,       Ahi, row0, K, k0, tid);
    stage_half(sbuf + OFF_ALO, Alo, row0, K, k0, tid);
    stage_half(sbuf + OFF_BHI, Bhi, col0, K, k0, tid);
    stage_half(sbuf + OFF_BLO, Blo, col0, K, k0, tid);
    asm volatile("cp.async.commit_group;" ::: "memory");
}

template<int EPI>
__global__ __launch_bounds__(256, 2)
void gemm_mma(const __nv_bfloat16* __restrict__ Ahi, const __nv_bfloat16* __restrict__ Alo,
              const __nv_bfloat16* __restrict__ Bhi, const __nv_bfloat16* __restrict__ Blo,
              int K, const float* __restrict__ bias,
              float* __restrict__ Cf, __nv_bfloat16* __restrict__ Chi,
              __nv_bfloat16* __restrict__ Clo,
              int ldc, size_t sA, size_t sB, size_t sC)
{
    extern __shared__ __align__(1024) char smem[];
    const uint32_t sb = smem_u32(smem);
    const int tid = threadIdx.x;
    const int bz  = blockIdx.z;
    Ahi += (size_t)bz * sA;  Alo += (size_t)bz * sA;
    Bhi += (size_t)bz * sB;  Blo += (size_t)bz * sB;
    if (EPI == 0) { Chi += (size_t)bz * sC; Clo += (size_t)bz * sC; }
    else          { Cf  += (size_t)bz * sC; }

    const size_t row0 = (size_t)blockIdx.y * TM;
    const size_t col0 = (size_t)blockIdx.x * TN;

    const int lane = tid & 31, warp = tid >> 5;
    const int wm = warp >> 2, wn = warp & 3;

    const uint32_t dlA = (uint32_t)((lane & 15) >> 1);
    const uint32_t baseA = (uint32_t)(wm * 32 + dlA) * 128;
    uint32_t chA[2];
    #pragma unroll
    for (int ks = 0; ks < 2; ks++)
        chA[ks] = ((((uint32_t)(lane & 1) << 2) + (uint32_t)(2 * ks + (lane >> 4))) ^ dlA) << 4;
    const uint32_t vB  = (uint32_t)((lane & 7) | ((lane >> 4) << 3));
    const uint32_t dlB = vB >> 1;
    const uint32_t baseB = (uint32_t)(wn * 16 + dlB) * 128;
    uint32_t chB[2];
    #pragma unroll
    for (int ks = 0; ks < 2; ks++)
        chB[ks] = ((((uint32_t)(lane & 1) << 2) + (uint32_t)(2 * ks + ((lane >> 3) & 1))) ^ dlB) << 4;

    float acc[4][4][4];
    #pragma unroll
    for (int i = 0; i < 4; i++)
        #pragma unroll
        for (int j = 0; j < 4; j++)
            #pragma unroll
            for (int q = 0; q < 4; q++) acc[i][j][q] = 0.0f;

    const int NS = K / KC;
    stage_all(sb + 0 * STG, Ahi, Alo, Bhi, Blo, row0, col0, K, 0,  tid);
    stage_all(sb + 1 * STG, Ahi, Alo, Bhi, Blo, row0, col0, K, KC, tid);

    int buf = 0;
    for (int st = 0; st < NS; st++) {
        if (st + 1 < NS) asm volatile("cp.async.wait_group 1;" ::: "memory");
        else             asm volatile("cp.async.wait_group 0;" ::: "memory");
        __syncthreads();

        const uint32_t sbuf = sb + (uint32_t)buf * STG;
        #pragma unroll
        for (int ks = 0; ks < 2; ks++) {
            uint32_t ah[4][4], al[4][4];
            #pragma unroll
            for (int am = 0; am < 4; am++) {
                ldsm4(sbuf + baseA + am * 1024 + chA[ks],
                      ah[am][0], ah[am][1], ah[am][2], ah[am][3]);
                ldsm4(sbuf + OFF_ALO + baseA + am * 1024 + chA[ks],
                      al[am][0], al[am][1], al[am][2], al[am][3]);
            }
            uint32_t bh[4][2], bl[4][2];
            #pragma unroll
            for (int p = 0; p < 2; p++) {
                uint32_t r0, r1, r2, r3;
                ldsm4(sbuf + OFF_BHI + baseB + p * 1024 + chB[ks], r0, r1, r2, r3);
                bh[2 * p][0] = r0; bh[2 * p][1] = r1;
                bh[2 * p + 1][0] = r2; bh[2 * p + 1][1] = r3;
                ldsm4(sbuf + OFF_BLO + baseB + p * 1024 + chB[ks], r0, r1, r2, r3);
                bl[2 * p][0] = r0; bl[2 * p][1] = r1;
                bl[2 * p + 1][0] = r2; bl[2 * p + 1][1] = r3;
            }
            #pragma unroll
            for (int am = 0; am < 4; am++)
                #pragma unroll
                for (int an = 0; an < 4; an++) {
                    mma16816(acc[am][an], ah[am], bh[an]);
                    mma16816(acc[am][an], ah[am], bl[an]);
                    mma16816(acc[am][an], al[am], bh[an]);
                }
        }

        if (st + 2 < NS) {
            int nb = buf + 2; if (nb >= NSTAGE) nb -= NSTAGE;
            stage_all(sb + (uint32_t)nb * STG, Ahi, Alo, Bhi, Blo,
                      row0, col0, K, (st + 2) * KC, tid);
        }
        if (++buf == NSTAGE) buf = 0;
    }

    const int re = (int)row0 + wm * 64 + (lane >> 2);
    const int ce = (int)col0 + wn * 32 + (lane & 3) * 2;
    #pragma unroll
    for (int am = 0; am < 4; am++) {
        #pragma unroll
        for (int an = 0; an < 4; an++) {
            const int r = re + am * 16;
            const int c = ce + an * 8;
            float v0 = acc[am][an][0], v1 = acc[am][an][1];
            float v2 = acc[am][an][2], v3 = acc[am][an][3];
            if (EPI == 1) {
                *(float2*)&Cf[(size_t)r * ldc + c]       = make_float2(v0, v1);
                *(float2*)&Cf[(size_t)(r + 8) * ldc + c] = make_float2(v2, v3);
            } else {
                const float bb0 = bias[c], bb1 = bias[c + 1];
                v0 += bb0; v1 += bb1; v2 += bb0; v3 += bb1;
                __nv_bfloat16 h0 = __float2bfloat16(v0), h1 = __float2bfloat16(v1);
                __nv_bfloat16 h2 = __float2bfloat16(v2), h3 = __float2bfloat16(v3);
                float l0 = v0 - __bfloat162float(h0);
                float l1 = v1 - __bfloat162float(h1);
                float l2 = v2 - __bfloat162float(h2);
                float l3 = v3 - __bfloat162float(h3);
                uint32_t hp0 = (uint32_t)__bfloat16_as_ushort(h0) |
                               ((uint32_t)__bfloat16_as_ushort(h1) << 16);
                uint32_t hp1 = (uint32_t)__bfloat16_as_ushort(h2) |
                               ((uint32_t)__bfloat16_as_ushort(h3) << 16);
                __nv_bfloat162 lp0 = __floats2bfloat162_rn(l0, l1);
                __nv_bfloat162 lp1 = __floats2bfloat162_rn(l2, l3);
                *(uint32_t*)&Chi[(size_t)r * ldc + c]       = hp0;
                *(uint32_t*)&Chi[(size_t)(r + 8) * ldc + c] = hp1;
                *(uint32_t*)&Clo[(size_t)r * ldc + c]       = *reinterpret_cast<uint32_t*>(&lp0);
                *(uint32_t*)&Clo[(size_t)(r + 8) * ldc + c] = *reinterpret_cast<uint32_t*>(&lp1);
            }
        }
    }
}

// ---------------------------------------------------------------------------
// Row softmax, diag masked; emits A as bf16 hi/lo.
// ---------------------------------------------------------------------------
__global__ __launch_bounds__(256)
void softmax_kernel(const float* __restrict__ G, __nv_bfloat16* __restrict__ Ah,
                    __nv_bfloat16* __restrict__ Al)
{
    const int l = blockIdx.x;
    const int b = blockIdx.y;
    const size_t rowoff = ((size_t)b * L_ + (size_t)l) * L_;
    const int tid = threadIdx.x;

    float4 v = ((const float4*)(G + rowoff))[tid];
    if ((l >> 2) == tid) (&v.x)[l & 3] -= 1e5f;

    float mx = fmaxf(fmaxf(v.x, v.y), fmaxf(v.z, v.w));

    __shared__ float red1[8];
    __shared__ float red2[8];
    #pragma unroll
    for (int o = 16; o > 0; o >>= 1)
        mx = fmaxf(mx, __shfl_xor_sync(0xffffffffu, mx, o));
    if ((tid & 31) == 0) red1[tid >> 5] = mx;
    __syncthreads();
    mx = red1[0];
    #pragma unroll
    for (int i = 1; i < 8; i++) mx = fmaxf(mx, red1[i]);

    v.x = __expf(v.x - mx); v.y = __expf(v.y - mx);
    v.z = __expf(v.z - mx); v.w = __expf(v.w - mx);
    float s = (v.x + v.y) + (v.z + v.w);
    #pragma unroll
    for (int o = 16; o > 0; o >>= 1)
        s += __shfl_xor_sync(0xffffffffu, s, o);
    if ((tid & 31) == 0) red2[tid >> 5] = s;
    __syncthreads();
    s = red2[0];
    #pragma unroll
    for (int i = 1; i < 8; i++) s += red2[i];

    const float inv = 1.0f / s;
    v.x *= inv; v.y *= inv; v.z *= inv; v.w *= inv;

    __nv_bfloat16 h0 = __float2bfloat16(v.x), h1 = __float2bfloat16(v.y);
    __nv_bfloat16 h2 = __float2bfloat16(v.z), h3 = __float2bfloat16(v.w);
    float l0 = v.x - __bfloat162float(h0);
    float l1 = v.y - __bfloat162float(h1);
    float l2 = v.z - __bfloat162float(h2);
    float l3 = v.w - __bfloat162float(h3);
    uint2 hv, lv;
    hv.x = (uint32_t)__bfloat16_as_ushort(h0) | ((uint32_t)__bfloat16_as_ushort(h1) << 16);
    hv.y = (uint32_t)__bfloat16_as_ushort(h2) | ((uint32_t)__bfloat16_as_ushort(h3) << 16);
    __nv_bfloat162 p01 = __floats2bfloat162_rn(l0, l1);
    __nv_bfloat162 p23 = __floats2bfloat162_rn(l2, l3);
    lv.x = *reinterpret_cast<uint32_t*>(&p01);
    lv.y = *reinterpret_cast<uint32_t*>(&p23);
    ((uint2*)(Ah + rowoff))[tid] = hv;
    ((uint2*)(Al + rowoff))[tid] = lv;
}

// ---------------------------------------------------------------------------
// B0 = (sup - colsum/total) * row_has (fp32);  u1 = B0 as bf16 hi/lo.
// ---------------------------------------------------------------------------
__global__ __launch_bounds__(1024)
void b0_kernel(const float* __restrict__ lab, float* __restrict__ B0,
               __nv_bfloat16* __restrict__ uh, __nv_bfloat16* __restrict__ ul)
{
    const int b = blockIdx.x;
    const int t = threadIdx.x;
    const float* supb = lab + (size_t)b * L_ * N_;

    __shared__ float colp[16][64];
    __shared__ float s_col[64];
    __shared__ float s_rh[L_];
    __shared__ float s_tot;

    if (t == 0) s_tot = 0.0f;

    {
        const int c = t & 63, g = t >> 6;
        float cp = 0.0f;
        #pragma unroll 4
        for (int i = 0; i < 64; i++)
            cp += supb[(size_t)(i * 16 + g) * N_ + c];
        colp[g][c] = cp;
    }
    {
        const int w = t >> 5, lane = t & 31;
        for (int r = w; r < L_; r += 32) {
            float v = supb[(size_t)r * N_ + lane] + supb[(size_t)r * N_ + 32 + lane];
            #pragma unroll
            for (int o = 16; o > 0; o >>= 1) v += __shfl_xor_sync(0xffffffffu, v, o);
            if (lane == 0) s_rh[r] = (v > 0.5f) ? 1.0f : 0.0f;
        }
    }
    __syncthreads();
    if (t < 64) {
        float s = 0.0f;
        #pragma unroll
        for (int j = 0; j < 16; j++) s += colp[j][t];
        s_col[t] = s;
    }
    {
        float v = s_rh[t];
        #pragma unroll
        for (int o = 16; o > 0; o >>= 1) v += __shfl_xor_sync(0xffffffffu, v, o);
        if ((t & 31) == 0) atomicAdd(&s_tot, v);
    }
    __syncthreads();

    const float inv = 1.0f / s_tot;
    const size_t boff = (size_t)b * L_ * N_;
    #pragma unroll 4
    for (int i = 0; i < 64; i++) {
        const int idx = t + i * 1024;
        const int r = idx >> 6, n = idx & 63;
        float v = (supb[idx] - s_col[n] * inv) * s_rh[r];
        B0[boff + idx] = v;
        __nv_bfloat16 h = __float2bfloat16(v);
        uh[boff + idx] = h;
        ul[boff + idx] = __float2bfloat16(v - __bfloat162float(h));
    }
}

// ---------------------------------------------------------------------------
// Tensor-core power-iteration step:
//   y[l,n] = sum_m A[m,l]*u[m,n];  v = y + B0 (+pred)
//   LAST=0: emit v as bf16 hi/lo (next iter input). LAST=1: emit fp32.
// A-op via ldmatrix.trans from [k=m][l] tiles; B-op via ldmatrix.trans from
// [k][n] u tiles. Block: 128 l x 64 n; 8 warps = 2(M:64 l) x 4(N:16 n).
// 3-stage cp.async ring. Grid (8, 1, 8).
// ---------------------------------------------------------------------------
#define IT_KC   32
#define IT_AL_OFF 8192
#define IT_UH_OFF 16384
#define IT_UL_OFF 20480
#define IT_STG  24576
#define IT_SMEM (3 * IT_STG)

__device__ __forceinline__ void it_stage(uint32_t sbuf,
        const __nv_bfloat16* __restrict__ Ah, const __nv_bfloat16* __restrict__ Al,
        const __nv_bfloat16* __restrict__ uh, const __nv_bfloat16* __restrict__ ul,
        int l0, int k0, int tid)
{
    // A tiles: 32 k-rows x 128 l (256B rows, 16 chunks), swizzle c ^ (k&15)
    #pragma unroll
    for (int i = 0; i < 2; i++) {
        int idx = tid + i * 256;
        int r = idx >> 4, c = idx & 15;
        uint32_t off = (uint32_t)r * 256 + ((uint32_t)(c ^ (r & 15)) << 4);
        const void* gp = Ah + (size_t)(k0 + r) * L_ + l0 + c * 8;
        cp16(sbuf + off, gp);
        const void* gq = Al + (size_t)(k0 + r) * L_ + l0 + c * 8;
        cp16(sbuf + IT_AL_OFF + off, gq);
    }
    // u tiles: 32 k-rows x 64 n (128B rows, 8 chunks), swizzle c ^ (k&7)
    {
        int r = tid >> 3, c = tid & 7;
        uint32_t off = (uint32_t)r * 128 + ((uint32_t)(c ^ (r & 7)) << 4);
        cp16(sbuf + IT_UH_OFF + off, uh + (size_t)(k0 + r) * N_ + c * 8);
        cp16(sbuf + IT_UL_OFF + off, ul + (size_t)(k0 + r) * N_ + c * 8);
    }
    asm volatile("cp.async.commit_group;" ::: "memory");
}

template<int LAST>
__global__ __launch_bounds__(256, 2)
void iter_mma(const __nv_bfloat16* __restrict__ Ah, const __nv_bfloat16* __restrict__ Al,
              const __nv_bfloat16* __restrict__ uh_in, const __nv_bfloat16* __restrict__ ul_in,
              const float* __restrict__ B0, const float* __restrict__ pred,
              __nv_bfloat16* __restrict__ uh_out, __nv_bfloat16* __restrict__ ul_out,
              float* __restrict__ f32out)
{
    extern __shared__ __align__(1024) char smem[];
    const uint32_t sb = smem_u32(smem);
    const int tid = threadIdx.x;
    const int b = blockIdx.z;
    const int l0 = blockIdx.x * 128;

    const __nv_bfloat16* Ahb = Ah + (size_t)b * L_ * L_;
    const __nv_bfloat16* Alb = Al + (size_t)b * L_ * L_;
    const __nv_bfloat16* uhb = uh_in + (size_t)b * L_ * N_;
    const __nv_bfloat16* ulb = ul_in + (size_t)b * L_ * N_;

    const int lane = tid & 31, warp = tid >> 5;
    const int wm = warp >> 2, wn = warp & 3;   // warp tile: 64 l x 16 n

    // ldmatrix.trans address precompute (stage-relative)
    uint32_t aoff[2][4];
    {
        uint32_t k_lane = (uint32_t)((lane & 7) + ((lane >> 4) << 3));
        uint32_t mbit = (uint32_t)((lane >> 3) & 1);
        #pragma unroll
        for (int ks = 0; ks < 2; ks++) {
            uint32_t k = (uint32_t)(ks * 16) + k_lane;
            #pragma unroll
            for (int am = 0; am < 4; am++) {
                uint32_t cA = (uint32_t)(wm * 8 + am * 2) + mbit;
                aoff[ks][am] = k * 256 + ((cA ^ (k & 15)) << 4);
            }
        }
    }
    uint32_t uoff[2];
    {
        uint32_t k_lane = (uint32_t)((lane & 7) + (((lane >> 3) & 1) << 3));
        uint32_t cn = (uint32_t)(wn * 2 + (lane >> 4));
        #pragma unroll
        for (int ks = 0; ks < 2; ks++) {
            uint32_t k = (uint32_t)(ks * 16) + k_lane;
            uoff[ks] = k * 128 + ((cn ^ (k & 7)) << 4);
        }
    }

    float acc[4][2][4];
    #pragma unroll
    for (int i = 0; i < 4; i++)
        #pragma unroll
        for (int j = 0; j < 2; j++)
            #pragma unroll
            for (int q = 0; q < 4; q++) acc[i][j][q] = 0.0f;

    const int NS = L_ / IT_KC;   // 32
    it_stage(sb + 0 * IT_STG, Ahb, Alb, uhb, ulb, l0, 0,      tid);
    it_stage(sb + 1 * IT_STG, Ahb, Alb, uhb, ulb, l0, IT_KC,  tid);

    int buf = 0;
    for (int st = 0; st < NS; st++) {
        if (st + 1 < NS) asm volatile("cp.async.wait_group 1;" ::: "memory");
        else             asm volatile("cp.async.wait_group 0;" ::: "memory");
        __syncthreads();

        const uint32_t sbuf = sb + (uint32_t)buf * IT_STG;
        #pragma unroll
        for (int ks = 0; ks < 2; ks++) {
            uint32_t ah[4][4], al4[4][4];
            #pragma unroll
            for (int am = 0; am < 4; am++) {
                ldsm4t(sbuf + aoff[ks][am],
                       ah[am][0], ah[am][1], ah[am][2], ah[am][3]);
                ldsm4t(sbuf + IT_AL_OFF + aoff[ks][am],
                       al4[am][0], al4[am][1], al4[am][2], al4[am][3]);
            }
            uint32_t bh[2][2], bl[2][2];
            {
                uint32_t r0, r1, r2, r3;
                ldsm4t(sbuf + IT_UH_OFF + uoff[ks], r0, r1, r2, r3);
                bh[0][0] = r0; bh[0][1] = r1; bh[1][0] = r2; bh[1][1] = r3;
                ldsm4t(sbuf + IT_UL_OFF + uoff[ks], r0, r1, r2, r3);
                bl[0][0] = r0; bl[0][1] = r1; bl[1][0] = r2; bl[1][1] = r3;
            }
            #pragma unroll
            for (int am = 0; am < 4; am++)
                #pragma unroll
                for (int an = 0; an < 2; an++) {
                    mma16816(acc[am][an], ah[am], bh[an]);
                    mma16816(acc[am][an], ah[am], bl[an]);
                    mma16816(acc[am][an], al4[am], bh[an]);
                }
        }

        if (st + 2 < NS) {
            int nb = buf + 2; if (nb >= 3) nb -= 3;
            it_stage(sb + (uint32_t)nb * IT_STG, Ahb, Alb, uhb, ulb,
                     l0, (st + 2) * IT_KC, tid);
        }
        if (++buf == 3) buf = 0;
    }

    // epilogue
    const int lbase = l0 + wm * 64 + (lane >> 2);
    const int nbase = wn * 16 + (lane & 3) * 2;
    #pragma unroll
    for (int am = 0; am < 4; am++) {
        #pragma unroll
        for (int an = 0; an < 2; an++) {
            const int l = lbase + am * 16;
            const int n = nbase + an * 8;
            const size_t o0 = ((size_t)b * L_ + l) * N_ + n;
            const size_t o1 = o0 + 8 * N_;
            float v0 = acc[am][an][0] + B0[o0];
            float v1 = acc[am][an][1] + B0[o0 + 1];
            float v2 = acc[am][an][2] + B0[o1];
            float v3 = acc[am][an][3] + B0[o1 + 1];
            if (pred) {
                v0 += pred[o0]; v1 += pred[o0 + 1];
                v2 += pred[o1]; v3 += pred[o1 + 1];
            }
            if (LAST) {
                *(float2*)&f32out[o0] = make_float2(v0, v1);
                *(float2*)&f32out[o1] = make_float2(v2, v3);
            } else {
                __nv_bfloat16 h0 = __float2bfloat16(v0), h1 = __float2bfloat16(v1);
                __nv_bfloat16 h2 = __float2bfloat16(v2), h3 = __float2bfloat16(v3);
                __nv_bfloat162 lo01 = __floats2bfloat162_rn(v0 - __bfloat162float(h0),
                                                            v1 - __bfloat162float(h1));
                __nv_bfloat162 lo23 = __floats2bfloat162_rn(v2 - __bfloat162float(h2),
                                                            v3 - __bfloat162float(h3));
                uint32_t hp0 = (uint32_t)__bfloat16_as_ushort(h0) |
                               ((uint32_t)__bfloat16_as_ushort(h1) << 16);
                uint32_t hp1 = (uint32_t)__bfloat16_as_ushort(h2) |
                               ((uint32_t)__bfloat16_as_ushort(h3) << 16);
                *(uint32_t*)&uh_out[o0] = hp0;
                *(uint32_t*)&uh_out[o1] = hp1;
                *(uint32_t*)&ul_out[o0] = *reinterpret_cast<uint32_t*>(&lo01);
                *(uint32_t*)&ul_out[o1] = *reinterpret_cast<uint32_t*>(&lo23);
            }
        }
    }
}

// ---------------------------------------------------------------------------
extern "C" void kernel_launch(void* const* d_in, const int* in_sizes, int n_in,
                              void* d_out, int out_size)
{
    const float* samples = (const float*)d_in[0];  // [8,1024,3072]
    const float* label   = (const float*)d_in[1];  // [8,1024,64]
    const float* predict = (const float*)d_in[2];  // [8,1024,64]
    const float* W       = (const float*)d_in[3];  // [1024,3072]
    const float* bproj   = (const float*)d_in[4];  // [1024]
    float* out = (float*)d_out;                    // [8,1024,64]

    __nv_bfloat16 *smph, *smpl, *Wh, *Wl, *sh, *sl, *uh1, *ul1, *uh2, *ul2;
    float *A, *B0;
    cudaGetSymbolAddress((void**)&smph, g_smp_hi);
    cudaGetSymbolAddress((void**)&smpl, g_smp_lo);
    cudaGetSymbolAddress((void**)&Wh,   g_W_hi);
    cudaGetSymbolAddress((void**)&Wl,   g_W_lo);
    cudaGetSymbolAddress((void**)&sh,   g_s_hi);
    cudaGetSymbolAddress((void**)&sl,   g_s_lo);
    cudaGetSymbolAddress((void**)&A,    g_A);
    cudaGetSymbolAddress((void**)&B0,   g_B0);
    cudaGetSymbolAddress((void**)&uh1,  g_uh1);
    cudaGetSymbolAddress((void**)&ul1,  g_ul1);
    cudaGetSymbolAddress((void**)&uh2,  g_uh2);
    cudaGetSymbolAddress((void**)&ul2,  g_ul2);

    cudaFuncSetAttribute(gemm_mma<0>, cudaFuncAttributeMaxDynamicSharedMemorySize, GEMM_SMEM);
    cudaFuncSetAttribute(gemm_mma<1>, cudaFuncAttributeMaxDynamicSharedMemorySize, GEMM_SMEM);
    cudaFuncSetAttribute(iter_mma<0>, cudaFuncAttributeMaxDynamicSharedMemorySize, IT_SMEM);
    cudaFuncSetAttribute(iter_mma<1>, cudaFuncAttributeMaxDynamicSharedMemorySize, IT_SMEM);

    const size_t LH = (size_t)L_ * H_;
    const size_t LL = (size_t)L_ * L_;

    // split fp32 -> bf16 hi/lo
    {
        int n4 = (B_ * L_ * K3_) / 4;
        split_kernel<<<(n4 + 255) / 256, 256>>>(samples, smph, smpl, n4);
        int w4 = (H_ * K3_) / 4;
        split_kernel<<<(w4 + 255) / 256, 256>>>(W, Wh, Wl, w4);
    }

    // s = samples @ W^T + b_proj  -> bf16 hi/lo
    gemm_mma<0><<<dim3(H_ / TN, (B_ * L_) / TM, 1), 256, GEMM_SMEM>>>(
        smph, smpl, Wh, Wl, K3_, bproj, nullptr, sh, sl, H_, 0, 0, 0);

    // graph[b] = s[b] @ s[b]^T  -> fp32
    gemm_mma<1><<<dim3(L_ / TN, L_ / TM, B_), 256, GEMM_SMEM>>>(
        sh, sl, sh, sl, H_, nullptr, A, nullptr, nullptr, L_, LH, LH, LL);

    // A = softmax(graph - 1e5*I), emitted as bf16 hi/lo (reuses s buffers)
    softmax_kernel<<<dim3(L_, B_), 256>>>(A, sh, sl);

    // B0 (fp32) + u(t=1) as bf16 hi/lo
    b0_kernel<<<B_, 1024>>>(label, B0, uh1, ul1);

    // t=2..6: u = A^T u + B0 (+ predict at t==3), tensor-core iterations
    dim3 ig(L_ / 128, 1, B_);
    iter_mma<0><<<ig, 256, IT_SMEM>>>(sh, sl, uh1, ul1, B0, nullptr,  uh2, ul2, nullptr); // t=2
    iter_mma<0><<<ig, 256, IT_SMEM>>>(sh, sl, uh2, ul2, B0, predict,  uh1, ul1, nullptr); // t=3
    iter_mma<0><<<ig, 256, IT_SMEM>>>(sh, sl, uh1, ul1, B0, nullptr,  uh2, ul2, nullptr); // t=4
    iter_mma<0><<<ig, 256, IT_SMEM>>>(sh, sl, uh2, ul2, B0, nullptr,  uh1, ul1, nullptr); // t=5
    iter_mma<1><<<ig, 256, IT_SMEM>>>(sh, sl, uh1, ul1, B0, nullptr,  nullptr, nullptr, out); // t=6
}

// round 10
// speedup vs baseline: 3.2600x; 1.0794x over previous
#include <cuda_runtime.h>
#include <cuda_bf16.h>
#include <cstddef>
#include <cstdint>

#define B_  8
#define L_  1024
#define H_  1024
#define K3_ 3072
#define N_  64

// ---------------------------------------------------------------------------
// Static scratch (no allocations allowed)
// ---------------------------------------------------------------------------
__device__ __align__(256) __nv_bfloat16 g_smp_hi[(size_t)B_ * L_ * K3_];
__device__ __align__(256) __nv_bfloat16 g_smp_lo[(size_t)B_ * L_ * K3_];
__device__ __align__(256) __nv_bfloat16 g_W_hi [(size_t)H_ * K3_];
__device__ __align__(256) __nv_bfloat16 g_W_lo [(size_t)H_ * K3_];
__device__ __align__(256) __nv_bfloat16 g_s_hi [(size_t)B_ * L_ * H_];  // later: A_hi
__device__ __align__(256) __nv_bfloat16 g_s_lo [(size_t)B_ * L_ * H_];  // later: A_lo
__device__ __align__(256) float g_A [(size_t)B_ * L_ * L_];             // graph (fp32)
__device__ __align__(256) float g_B0[(size_t)B_ * L_ * N_];
__device__ __align__(256) __nv_bfloat16 g_uh1[(size_t)B_ * L_ * N_];
__device__ __align__(256) __nv_bfloat16 g_ul1[(size_t)B_ * L_ * N_];
__device__ __align__(256) __nv_bfloat16 g_uh2[(size_t)B_ * L_ * N_];
__device__ __align__(256) __nv_bfloat16 g_ul2[(size_t)B_ * L_ * N_];

// ---------------------------------------------------------------------------
// PTX helpers (baseline-PTX only: cp.async / ldmatrix / mma.sync)
// ---------------------------------------------------------------------------
__device__ __forceinline__ uint32_t smem_u32(const void* p) {
    uint32_t a;
    asm("{ .reg .u64 t; cvta.to.shared.u64 t, %1; cvt.u32.u64 %0, t; }" : "=r"(a) : "l"(p));
    return a;
}

__device__ __forceinline__ void cp16(uint32_t saddr, const void* g) {
    asm volatile("cp.async.cg.shared.global [%0], [%1], 16;" :: "r"(saddr), "l"(g) : "memory");
}

__device__ __forceinline__ void ldsm4(uint32_t addr, uint32_t& r0, uint32_t& r1,
                                      uint32_t& r2, uint32_t& r3) {
    asm volatile("ldmatrix.sync.aligned.m8n8.x4.shared.b16 {%0,%1,%2,%3}, [%4];"
                 : "=r"(r0), "=r"(r1), "=r"(r2), "=r"(r3) : "r"(addr));
}

__device__ __forceinline__ void ldsm4t(uint32_t addr, uint32_t& r0, uint32_t& r1,
                                       uint32_t& r2, uint32_t& r3) {
    asm volatile("ldmatrix.sync.aligned.m8n8.x4.trans.shared.b16 {%0,%1,%2,%3}, [%4];"
                 : "=r"(r0), "=r"(r1), "=r"(r2), "=r"(r3) : "r"(addr));
}

__device__ __forceinline__ void mma16816(float* c, const uint32_t* a, const uint32_t* b) {
    asm volatile(
        "mma.sync.aligned.m16n8k16.row.col.f32.bf16.bf16.f32 "
        "{%0,%1,%2,%3}, {%4,%5,%6,%7}, {%8,%9}, {%0,%1,%2,%3};"
        : "+f"(c[0]), "+f"(c[1]), "+f"(c[2]), "+f"(c[3])
        : "r"(a[0]), "r"(a[1]), "r"(a[2]), "r"(a[3]), "r"(b[0]), "r"(b[1]));
}

// ---------------------------------------------------------------------------
// fp32 -> bf16 hi/lo split
// ---------------------------------------------------------------------------
__global__ __launch_bounds__(256)
void split_kernel(const float* __restrict__ x, __nv_bfloat16* __restrict__ hi,
                  __nv_bfloat16* __restrict__ lo, int n4)
{
    int i = blockIdx.x * blockDim.x + threadIdx.x;
    if (i >= n4) return;
    float4 v = ((const float4*)x)[i];
    __nv_bfloat16 h0 = __float2bfloat16(v.x), h1 = __float2bfloat16(v.y);
    __nv_bfloat16 h2 = __float2bfloat16(v.z), h3 = __float2bfloat16(v.w);
    float r0 = v.x - __bfloat162float(h0);
    float r1 = v.y - __bfloat162float(h1);
    float r2 = v.z - __bfloat162float(h2);
    float r3 = v.w - __bfloat162float(h3);
    uint2 hv, lv;
    hv.x = (uint32_t)__bfloat16_as_ushort(h0) | ((uint32_t)__bfloat16_as_ushort(h1) << 16);
    hv.y = (uint32_t)__bfloat16_as_ushort(h2) | ((uint32_t)__bfloat16_as_ushort(h3) << 16);
    __nv_bfloat162 l01 = __floats2bfloat162_rn(r0, r1);
    __nv_bfloat162 l23 = __floats2bfloat162_rn(r2, r3);
    lv.x = *reinterpret_cast<uint32_t*>(&l01);
    lv.y = *reinterpret_cast<uint32_t*>(&l23);
    ((uint2*)hi)[i] = hv;
    ((uint2*)lo)[i] = lv;
}

// ---------------------------------------------------------------------------
// Shared staging helper: (ITERS*64) rows x 32k bf16 tile, paired-row swizzle
// ---------------------------------------------------------------------------
template<int ITERS>
__device__ __forceinline__ void stage_rows(uint32_t sdst, const __nv_bfloat16* __restrict__ g,
                                           size_t row0, int ldk, int k0, int tid)
{
    #pragma unroll
    for (int i = 0; i < ITERS; i++) {
        int idx = tid + i * 256;
        int r = idx >> 2, c = idx & 3;
        const void* gp = g + (row0 + (size_t)r) * (size_t)ldk + k0 + c * 8;
        uint32_t line = (uint32_t)(r >> 1);
        uint32_t off = line * 128 + ((((uint32_t)(r & 1) * 4 + (uint32_t)c) ^ (line & 7)) << 4);
        cp16(sdst + off, gp);
    }
}

// ===========================================================================
// gemm_proj: s = samples @ W^T + bias -> bf16 hi/lo.
// Block 128(M) x 256(N), warp tile 64x64 (8 warps = 2x4), KC=32, 3-stage ring.
// ===========================================================================
#define P_ALO 8192
#define P_BHI 16384
#define P_BLO 32768
#define P_STG 49152
#define P_SMEM (3 * P_STG)

__global__ __launch_bounds__(256, 1)
void gemm_proj(const __nv_bfloat16* __restrict__ Ahi, const __nv_bfloat16* __restrict__ Alo,
               const __nv_bfloat16* __restrict__ Bhi, const __nv_bfloat16* __restrict__ Blo,
               const float* __restrict__ bias,
               __nv_bfloat16* __restrict__ Chi, __nv_bfloat16* __restrict__ Clo)
{
    extern __shared__ __align__(1024) char smem[];
    const uint32_t sb = smem_u32(smem);
    const int tid = threadIdx.x;
    const size_t row0 = (size_t)blockIdx.y * 128;
    const size_t col0 = (size_t)blockIdx.x * 256;
    const int K = K3_;

    const int lane = tid & 31, warp = tid >> 5;
    const int wm = warp >> 2, wn = warp & 3;

    const uint32_t dlA = (uint32_t)((lane & 15) >> 1);
    const uint32_t baseA = (uint32_t)(wm * 32 + dlA) * 128;
    uint32_t chA[2];
    #pragma unroll
    for (int ks = 0; ks < 2; ks++)
        chA[ks] = ((((uint32_t)(lane & 1) << 2) + (uint32_t)(2 * ks + (lane >> 4))) ^ dlA) << 4;
    const uint32_t vB  = (uint32_t)((lane & 7) | ((lane >> 4) << 3));
    const uint32_t dlB = vB >> 1;
    const uint32_t baseB = (uint32_t)(wn * 32 + dlB) * 128;
    uint32_t chB[2];
    #pragma unroll
    for (int ks = 0; ks < 2; ks++)
        chB[ks] = ((((uint32_t)(lane & 1) << 2) + (uint32_t)(2 * ks + ((lane >> 3) & 1))) ^ dlB) << 4;

    float acc[4][8][4];
    #pragma unroll
    for (int i = 0; i < 4; i++)
        #pragma unroll
        for (int j = 0; j < 8; j++)
            #pragma unroll
            for (int q = 0; q < 4; q++) acc[i][j][q] = 0.0f;

    const int NS = K / 32;
    {
        uint32_t s0 = sb, s1 = sb + P_STG;
        stage_rows<2>(s0 + 0,     Ahi, row0, K, 0, tid);
        stage_rows<2>(s0 + P_ALO, Alo, row0, K, 0, tid);
        stage_rows<4>(s0 + P_BHI, Bhi, col0, K, 0, tid);
        stage_rows<4>(s0 + P_BLO, Blo, col0, K, 0, tid);
        asm volatile("cp.async.commit_group;" ::: "memory");
        stage_rows<2>(s1 + 0,     Ahi, row0, K, 32, tid);
        stage_rows<2>(s1 + P_ALO, Alo, row0, K, 32, tid);
        stage_rows<4>(s1 + P_BHI, Bhi, col0, K, 32, tid);
        stage_rows<4>(s1 + P_BLO, Blo, col0, K, 32, tid);
        asm volatile("cp.async.commit_group;" ::: "memory");
    }

    int buf = 0;
    for (int st = 0; st < NS; st++) {
        if (st + 1 < NS) asm volatile("cp.async.wait_group 1;" ::: "memory");
        else             asm volatile("cp.async.wait_group 0;" ::: "memory");
        __syncthreads();

        const uint32_t sbuf = sb + (uint32_t)buf * P_STG;
        #pragma unroll
        for (int ks = 0; ks < 2; ks++) {
            uint32_t ah[4][4], al[4][4];
            #pragma unroll
            for (int am = 0; am < 4; am++) {
                ldsm4(sbuf + baseA + am * 1024 + chA[ks],
                      ah[am][0], ah[am][1], ah[am][2], ah[am][3]);
                ldsm4(sbuf + P_ALO + baseA + am * 1024 + chA[ks],
                      al[am][0], al[am][1], al[am][2], al[am][3]);
            }
            uint32_t bh[8][2], bl[8][2];
            #pragma unroll
            for (int p = 0; p < 4; p++) {
                uint32_t r0, r1, r2, r3;
                ldsm4(sbuf + P_BHI + baseB + p * 1024 + chB[ks], r0, r1, r2, r3);
                bh[2 * p][0] = r0; bh[2 * p][1] = r1;
                bh[2 * p + 1][0] = r2; bh[2 * p + 1][1] = r3;
                ldsm4(sbuf + P_BLO + baseB + p * 1024 + chB[ks], r0, r1, r2, r3);
                bl[2 * p][0] = r0; bl[2 * p][1] = r1;
                bl[2 * p + 1][0] = r2; bl[2 * p + 1][1] = r3;
            }
            #pragma unroll
            for (int am = 0; am < 4; am++)
                #pragma unroll
                for (int an = 0; an < 8; an++) {
                    mma16816(acc[am][an], ah[am], bh[an]);
                    mma16816(acc[am][an], ah[am], bl[an]);
                    mma16816(acc[am][an], al[am], bh[an]);
                }
        }

        if (st + 2 < NS) {
            int nb = buf + 2; if (nb >= 3) nb -= 3;
            const uint32_t np = sb + (uint32_t)nb * P_STG;
            const int k0 = (st + 2) * 32;
            stage_rows<2>(np + 0,     Ahi, row0, K, k0, tid);
            stage_rows<2>(np + P_ALO, Alo, row0, K, k0, tid);
            stage_rows<4>(np + P_BHI, Bhi, col0, K, k0, tid);
            stage_rows<4>(np + P_BLO, Blo, col0, K, k0, tid);
            asm volatile("cp.async.commit_group;" ::: "memory");
        }
        if (++buf == 3) buf = 0;
    }

    const int re = (int)row0 + wm * 64 + (lane >> 2);
    const int ce = (int)col0 + wn * 64 + (lane & 3) * 2;
    #pragma unroll
    for (int am = 0; am < 4; am++) {
        #pragma unroll
        for (int an = 0; an < 8; an++) {
            const int r = re + am * 16;
            const int c = ce + an * 8;
            float v0 = acc[am][an][0] + bias[c];
            float v1 = acc[am][an][1] + bias[c + 1];
            float v2 = acc[am][an][2] + bias[c];
            float v3 = acc[am][an][3] + bias[c + 1];
            __nv_bfloat16 h0 = __float2bfloat16(v0), h1 = __float2bfloat16(v1);
            __nv_bfloat16 h2 = __float2bfloat16(v2), h3 = __float2bfloat16(v3);
            __nv_bfloat162 lp0 = __floats2bfloat162_rn(v0 - __bfloat162float(h0),
                                                       v1 - __bfloat162float(h1));
            __nv_bfloat162 lp1 = __floats2bfloat162_rn(v2 - __bfloat162float(h2),
                                                       v3 - __bfloat162float(h3));
            uint32_t hp0 = (uint32_t)__bfloat16_as_ushort(h0) |
                           ((uint32_t)__bfloat16_as_ushort(h1) << 16);
            uint32_t hp1 = (uint32_t)__bfloat16_as_ushort(h2) |
                           ((uint32_t)__bfloat16_as_ushort(h3) << 16);
            *(uint32_t*)&Chi[(size_t)r * H_ + c]       = hp0;
            *(uint32_t*)&Chi[(size_t)(r + 8) * H_ + c] = hp1;
            *(uint32_t*)&Clo[(size_t)r * H_ + c]       = *reinterpret_cast<uint32_t*>(&lp0);
            *(uint32_t*)&Clo[(size_t)(r + 8) * H_ + c] = *reinterpret_cast<uint32_t*>(&lp1);
        }
    }
}

// ===========================================================================
// gemm_sym: graph[b] = s[b] @ s[b]^T (fp32), upper-tri tiles + mirror write.
// Block 128x128, warp 64x32, KC=32, 3-stage ring, 2 CTAs/SM.
// ===========================================================================
#define S_ALO 8192
#define S_BHI 16384
#define S_BLO 24576
#define S_STG 32768
#define S_SMEM (3 * S_STG)

__global__ __launch_bounds__(256, 2)
void gemm_sym(const __nv_bfloat16* __restrict__ sh, const __nv_bfloat16* __restrict__ sl,
              float* __restrict__ G)
{
    extern __shared__ __align__(1024) char smem[];
    const uint32_t sb = smem_u32(smem);
    const int tid = threadIdx.x;
    const int bz  = blockIdx.z;
    const int K = H_;

    int by = 0, rem = blockIdx.x;
    #pragma unroll
    for (int i = 0; i < 8; i++) {
        if (rem >= 8 - by) { rem -= (8 - by); by++; }
    }
    const int bx = by + rem;

    const __nv_bfloat16* Ahi = sh + (size_t)bz * L_ * H_;
    const __nv_bfloat16* Alo = sl + (size_t)bz * L_ * H_;
    float* Gb = G + (size_t)bz * L_ * L_;

    const size_t row0 = (size_t)by * 128;
    const size_t col0 = (size_t)bx * 128;

    const int lane = tid & 31, warp = tid >> 5;
    const int wm = warp >> 2, wn = warp & 3;

    const uint32_t dlA = (uint32_t)((lane & 15) >> 1);
    const uint32_t baseA = (uint32_t)(wm * 32 + dlA) * 128;
    uint32_t chA[2];
    #pragma unroll
    for (int ks = 0; ks < 2; ks++)
        chA[ks] = ((((uint32_t)(lane & 1) << 2) + (uint32_t)(2 * ks + (lane >> 4))) ^ dlA) << 4;
    const uint32_t vB  = (uint32_t)((lane & 7) | ((lane >> 4) << 3));
    const uint32_t dlB = vB >> 1;
    const uint32_t baseB = (uint32_t)(wn * 16 + dlB) * 128;
    uint32_t chB[2];
    #pragma unroll
    for (int ks = 0; ks < 2; ks++)
        chB[ks] = ((((uint32_t)(lane & 1) << 2) + (uint32_t)(2 * ks + ((lane >> 3) & 1))) ^ dlB) << 4;

    float acc[4][4][4];
    #pragma unroll
    for (int i = 0; i < 4; i++)
        #pragma unroll
        for (int j = 0; j < 4; j++)
            #pragma unroll
            for (int q = 0; q < 4; q++) acc[i][j][q] = 0.0f;

    const int NS = K / 32;
    {
        uint32_t s0 = sb, s1 = sb + S_STG;
        stage_rows<2>(s0 + 0,     Ahi, row0, K, 0, tid);
        stage_rows<2>(s0 + S_ALO, Alo, row0, K, 0, tid);
        stage_rows<2>(s0 + S_BHI, Ahi, col0, K, 0, tid);
        stage_rows<2>(s0 + S_BLO, Alo, col0, K, 0, tid);
        asm volatile("cp.async.commit_group;" ::: "memory");
        stage_rows<2>(s1 + 0,     Ahi, row0, K, 32, tid);
        stage_rows<2>(s1 + S_ALO, Alo, row0, K, 32, tid);
        stage_rows<2>(s1 + S_BHI, Ahi, col0, K, 32, tid);
        stage_rows<2>(s1 + S_BLO, Alo, col0, K, 32, tid);
        asm volatile("cp.async.commit_group;" ::: "memory");
    }

    int buf = 0;
    for (int st = 0; st < NS; st++) {
        if (st + 1 < NS) asm volatile("cp.async.wait_group 1;" ::: "memory");
        else             asm volatile("cp.async.wait_group 0;" ::: "memory");
        __syncthreads();

        const uint32_t sbuf = sb + (uint32_t)buf * S_STG;
        #pragma unroll
        for (int ks = 0; ks < 2; ks++) {
            uint32_t ah[4][4], al[4][4];
            #pragma unroll
            for (int am = 0; am < 4; am++) {
                ldsm4(sbuf + baseA + am * 1024 + chA[ks],
                      ah[am][0], ah[am][1], ah[am][2], ah[am][3]);
                ldsm4(sbuf + S_ALO + baseA + am * 1024 + chA[ks],
                      al[am][0], al[am][1], al[am][2], al[am][3]);
            }
            uint32_t bh[4][2], bl[4][2];
            #pragma unroll
            for (int p = 0; p < 2; p++) {
                uint32_t r0, r1, r2, r3;
                ldsm4(sbuf + S_BHI + baseB + p * 1024 + chB[ks], r0, r1, r2, r3);
                bh[2 * p][0] = r0; bh[2 * p][1] = r1;
                bh[2 * p + 1][0] = r2; bh[2 * p + 1][1] = r3;
                ldsm4(sbuf + S_BLO + baseB + p * 1024 + chB[ks], r0, r1, r2, r3);
                bl[2 * p][0] = r0; bl[2 * p][1] = r1;
                bl[2 * p + 1][0] = r2; bl[2 * p + 1][1] = r3;
            }
            #pragma unroll
            for (int am = 0; am < 4; am++)
                #pragma unroll
                for (int an = 0; an < 4; an++) {
                    mma16816(acc[am][an], ah[am], bh[an]);
                    mma16816(acc[am][an], ah[am], bl[an]);
                    mma16816(acc[am][an], al[am], bh[an]);
                }
        }

        if (st + 2 < NS) {
            int nb = buf + 2; if (nb >= 3) nb -= 3;
            const uint32_t np = sb + (uint32_t)nb * S_STG;
            const int k0 = (st + 2) * 32;
            stage_rows<2>(np + 0,     Ahi, row0, K, k0, tid);
            stage_rows<2>(np + S_ALO, Alo, row0, K, k0, tid);
            stage_rows<2>(np + S_BHI, Ahi, col0, K, k0, tid);
            stage_rows<2>(np + S_BLO, Alo, col0, K, k0, tid);
            asm volatile("cp.async.commit_group;" ::: "memory");
        }
        if (++buf == 3) buf = 0;
    }

    // R9 bug fix: all warps must finish reading the smem ring before it is
    // reused as the fp32 transpose staging buffer below.
    __syncthreads();

    const int rl = wm * 64 + (lane >> 2);
    const int cl = wn * 32 + (lane & 3) * 2;
    float* eb = (float*)smem;     // 128 x 129 fp32 staging (66 KB < 96 KB ring)
    #pragma unroll
    for (int am = 0; am < 4; am++) {
        #pragma unroll
        for (int an = 0; an < 4; an++) {
            const int r = rl + am * 16;
            const int c = cl + an * 8;
            float v0 = acc[am][an][0], v1 = acc[am][an][1];
            float v2 = acc[am][an][2], v3 = acc[am][an][3];
            *(float2*)&Gb[(row0 + r) * L_ + col0 + c]     = make_float2(v0, v1);
            *(float2*)&Gb[(row0 + r + 8) * L_ + col0 + c] = make_float2(v2, v3);
            if (bx != by) {
                eb[r * 129 + c] = v0;       eb[r * 129 + c + 1] = v1;
                eb[(r + 8) * 129 + c] = v2; eb[(r + 8) * 129 + c + 1] = v3;
            }
        }
    }
    if (bx != by) {
        __syncthreads();
        #pragma unroll 4
        for (int it = 0; it < 64; it++) {
            int idx = tid + it * 256;
            int j = idx >> 7, i = idx & 127;
            Gb[(col0 + j) * L_ + row0 + i] = eb[i * 129 + j];
        }
    }
}

// ---------------------------------------------------------------------------
// Row softmax, diag masked; emits A as bf16 hi/lo.
// ---------------------------------------------------------------------------
__global__ __launch_bounds__(256)
void softmax_kernel(const float* __restrict__ G, __nv_bfloat16* __restrict__ Ah,
                    __nv_bfloat16* __restrict__ Al)
{
    const int l = blockIdx.x;
    const int b = blockIdx.y;
    const size_t rowoff = ((size_t)b * L_ + (size_t)l) * L_;
    const int tid = threadIdx.x;

    float4 v = ((const float4*)(G + rowoff))[tid];
    if ((l >> 2) == tid) (&v.x)[l & 3] -= 1e5f;

    float mx = fmaxf(fmaxf(v.x, v.y), fmaxf(v.z, v.w));

    __shared__ float red1[8];
    __shared__ float red2[8];
    #pragma unroll
    for (int o = 16; o > 0; o >>= 1)
        mx = fmaxf(mx, __shfl_xor_sync(0xffffffffu, mx, o));
    if ((tid & 31) == 0) red1[tid >> 5] = mx;
    __syncthreads();
    mx = red1[0];
    #pragma unroll
    for (int i = 1; i < 8; i++) mx = fmaxf(mx, red1[i]);

    v.x = __expf(v.x - mx); v.y = __expf(v.y - mx);
    v.z = __expf(v.z - mx); v.w = __expf(v.w - mx);
    float s = (v.x + v.y) + (v.z + v.w);
    #pragma unroll
    for (int o = 16; o > 0; o >>= 1)
        s += __shfl_xor_sync(0xffffffffu, s, o);
    if ((tid & 31) == 0) red2[tid >> 5] = s;
    __syncthreads();
    s = red2[0];
    #pragma unroll
    for (int i = 1; i < 8; i++) s += red2[i];

    const float inv = 1.0f / s;
    v.x *= inv; v.y *= inv; v.z *= inv; v.w *= inv;

    __nv_bfloat16 h0 = __float2bfloat16(v.x), h1 = __float2bfloat16(v.y);
    __nv_bfloat16 h2 = __float2bfloat16(v.z), h3 = __float2bfloat16(v.w);
    float l0 = v.x - __bfloat162float(h0);
    float l1 = v.y - __bfloat162float(h1);
    float l2 = v.z - __bfloat162float(h2);
    float l3 = v.w - __bfloat162float(h3);
    uint2 hv, lv;
    hv.x = (uint32_t)__bfloat16_as_ushort(h0) | ((uint32_t)__bfloat16_as_ushort(h1) << 16);
    hv.y = (uint32_t)__bfloat16_as_ushort(h2) | ((uint32_t)__bfloat16_as_ushort(h3) << 16);
    __nv_bfloat162 p01 = __floats2bfloat162_rn(l0, l1);
    __nv_bfloat162 p23 = __floats2bfloat162_rn(l2, l3);
    lv.x = *reinterpret_cast<uint32_t*>(&p01);
    lv.y = *reinterpret_cast<uint32_t*>(&p23);
    ((uint2*)(Ah + rowoff))[tid] = hv;
    ((uint2*)(Al + rowoff))[tid] = lv;
}

// ---------------------------------------------------------------------------
// B0 = (sup - colsum/total) * row_has (fp32);  u1 = B0 as bf16 hi/lo.
// ---------------------------------------------------------------------------
__global__ __launch_bounds__(1024)
void b0_kernel(const float* __restrict__ lab, float* __restrict__ B0,
               __nv_bfloat16* __restrict__ uh, __nv_bfloat16* __restrict__ ul)
{
    const int b = blockIdx.x;
    const int t = threadIdx.x;
    const float* supb = lab + (size_t)b * L_ * N_;

    __shared__ float colp[16][64];
    __shared__ float s_col[64];
    __shared__ float s_rh[L_];
    __shared__ float s_tot;

    if (t == 0) s_tot = 0.0f;

    {
        const int c = t & 63, g = t >> 6;
        float cp = 0.0f;
        #pragma unroll 4
        for (int i = 0; i < 64; i++)
            cp += supb[(size_t)(i * 16 + g) * N_ + c];
        colp[g][c] = cp;
    }
    {
        const int w = t >> 5, lane = t & 31;
        for (int r = w; r < L_; r += 32) {
            float v = supb[(size_t)r * N_ + lane] + supb[(size_t)r * N_ + 32 + lane];
            #pragma unroll
            for (int o = 16; o > 0; o >>= 1) v += __shfl_xor_sync(0xffffffffu, v, o);
            if (lane == 0) s_rh[r] = (v > 0.5f) ? 1.0f : 0.0f;
        }
    }
    __syncthreads();
    if (t < 64) {
        float s = 0.0f;
        #pragma unroll
        for (int j = 0; j < 16; j++) s += colp[j][t];
        s_col[t] = s;
    }
    {
        float v = s_rh[t];
        #pragma unroll
        for (int o = 16; o > 0; o >>= 1) v += __shfl_xor_sync(0xffffffffu, v, o);
        if ((t & 31) == 0) atomicAdd(&s_tot, v);
    }
    __syncthreads();

    const float inv = 1.0f / s_tot;
    const size_t boff = (size_t)b * L_ * N_;
    #pragma unroll 4
    for (int i = 0; i < 64; i++) {
        const int idx = t + i * 1024;
        const int r = idx >> 6, n = idx & 63;
        float v = (supb[idx] - s_col[n] * inv) * s_rh[r];
        B0[boff + idx] = v;
        __nv_bfloat16 h = __float2bfloat16(v);
        uh[boff + idx] = h;
        ul[boff + idx] = __float2bfloat16(v - __bfloat162float(h));
    }
}

// ---------------------------------------------------------------------------
// Tensor-core power-iteration step (unchanged, known-good from R8).
// ---------------------------------------------------------------------------
#define IT_KC   32
#define IT_AL_OFF 8192
#define IT_UH_OFF 16384
#define IT_UL_OFF 20480
#define IT_STG  24576
#define IT_SMEM (3 * IT_STG)

__device__ __forceinline__ void it_stage(uint32_t sbuf,
        const __nv_bfloat16* __restrict__ Ah, const __nv_bfloat16* __restrict__ Al,
        const __nv_bfloat16* __restrict__ uh, const __nv_bfloat16* __restrict__ ul,
        int l0, int k0, int tid)
{
    #pragma unroll
    for (int i = 0; i < 2; i++) {
        int idx = tid + i * 256;
        int r = idx >> 4, c = idx & 15;
        uint32_t off = (uint32_t)r * 256 + ((uint32_t)(c ^ (r & 15)) << 4);
        const void* gp = Ah + (size_t)(k0 + r) * L_ + l0 + c * 8;
        cp16(sbuf + off, gp);
        const void* gq = Al + (size_t)(k0 + r) * L_ + l0 + c * 8;
        cp16(sbuf + IT_AL_OFF + off, gq);
    }
    {
        int r = tid >> 3, c = tid & 7;
        uint32_t off = (uint32_t)r * 128 + ((uint32_t)(c ^ (r & 7)) << 4);
        cp16(sbuf + IT_UH_OFF + off, uh + (size_t)(k0 + r) * N_ + c * 8);
        cp16(sbuf + IT_UL_OFF + off, ul + (size_t)(k0 + r) * N_ + c * 8);
    }
    asm volatile("cp.async.commit_group;" ::: "memory");
}

template<int LAST>
__global__ __launch_bounds__(256, 2)
void iter_mma(const __nv_bfloat16* __restrict__ Ah, const __nv_bfloat16* __restrict__ Al,
              const __nv_bfloat16* __restrict__ uh_in, const __nv_bfloat16* __restrict__ ul_in,
              const float* __restrict__ B0, const float* __restrict__ pred,
              __nv_bfloat16* __restrict__ uh_out, __nv_bfloat16* __restrict__ ul_out,
              float* __restrict__ f32out)
{
    extern __shared__ __align__(1024) char smem[];
    const uint32_t sb = smem_u32(smem);
    const int tid = threadIdx.x;
    const int b = blockIdx.z;
    const int l0 = blockIdx.x * 128;

    const __nv_bfloat16* Ahb = Ah + (size_t)b * L_ * L_;
    const __nv_bfloat16* Alb = Al + (size_t)b * L_ * L_;
    const __nv_bfloat16* uhb = uh_in + (size_t)b * L_ * N_;
    const __nv_bfloat16* ulb = ul_in + (size_t)b * L_ * N_;

    const int lane = tid & 31, warp = tid >> 5;
    const int wm = warp >> 2, wn = warp & 3;

    uint32_t aoff[2][4];
    {
        uint32_t k_lane = (uint32_t)((lane & 7) + ((lane >> 4) << 3));
        uint32_t mbit = (uint32_t)((lane >> 3) & 1);
        #pragma unroll
        for (int ks = 0; ks < 2; ks++) {
            uint32_t k = (uint32_t)(ks * 16) + k_lane;
            #pragma unroll
            for (int am = 0; am < 4; am++) {
                uint32_t cA = (uint32_t)(wm * 8 + am * 2) + mbit;
                aoff[ks][am] = k * 256 + ((cA ^ (k & 15)) << 4);
            }
        }
    }
    uint32_t uoff[2];
    {
        uint32_t k_lane = (uint32_t)((lane & 7) + (((lane >> 3) & 1) << 3));
        uint32_t cn = (uint32_t)(wn * 2 + (lane >> 4));
        #pragma unroll
        for (int ks = 0; ks < 2; ks++) {
            uint32_t k = (uint32_t)(ks * 16) + k_lane;
            uoff[ks] = k * 128 + ((cn ^ (k & 7)) << 4);
        }
    }

    float acc[4][2][4];
    #pragma unroll
    for (int i = 0; i < 4; i++)
        #pragma unroll
        for (int j = 0; j < 2; j++)
            #pragma unroll
            for (int q = 0; q < 4; q++) acc[i][j][q] = 0.0f;

    const int NS = L_ / IT_KC;
    it_stage(sb + 0 * IT_STG, Ahb, Alb, uhb, ulb, l0, 0,      tid);
    it_stage(sb + 1 * IT_STG, Ahb, Alb, uhb, ulb, l0, IT_KC,  tid);

    int buf = 0;
    for (int st = 0; st < NS; st++) {
        if (st + 1 < NS) asm volatile("cp.async.wait_group 1;" ::: "memory");
        else             asm volatile("cp.async.wait_group 0;" ::: "memory");
        __syncthreads();

        const uint32_t sbuf = sb + (uint32_t)buf * IT_STG;
        #pragma unroll
        for (int ks = 0; ks < 2; ks++) {
            uint32_t ah[4][4], al4[4][4];
            #pragma unroll
            for (int am = 0; am < 4; am++) {
                ldsm4t(sbuf + aoff[ks][am],
                       ah[am][0], ah[am][1], ah[am][2], ah[am][3]);
                ldsm4t(sbuf + IT_AL_OFF + aoff[ks][am],
                       al4[am][0], al4[am][1], al4[am][2], al4[am][3]);
            }
            uint32_t bh[2][2], bl[2][2];
            {
                uint32_t r0, r1, r2, r3;
                ldsm4t(sbuf + IT_UH_OFF + uoff[ks], r0, r1, r2, r3);
                bh[0][0] = r0; bh[0][1] = r1; bh[1][0] = r2; bh[1][1] = r3;
                ldsm4t(sbuf + IT_UL_OFF + uoff[ks], r0, r1, r2, r3);
                bl[0][0] = r0; bl[0][1] = r1; bl[1][0] = r2; bl[1][1] = r3;
            }
            #pragma unroll
            for (int am = 0; am < 4; am++)
                #pragma unroll
                for (int an = 0; an < 2; an++) {
                    mma16816(acc[am][an], ah[am], bh[an]);
                    mma16816(acc[am][an], ah[am], bl[an]);
                    mma16816(acc[am][an], al4[am], bh[an]);
                }
        }

        if (st + 2 < NS) {
            int nb = buf + 2; if (nb >= 3) nb -= 3;
            it_stage(sb + (uint32_t)nb * IT_STG, Ahb, Alb, uhb, ulb,
                     l0, (st + 2) * IT_KC, tid);
        }
        if (++buf == 3) buf = 0;
    }

    const int lbase = l0 + wm * 64 + (lane >> 2);
    const int nbase = wn * 16 + (lane & 3) * 2;
    #pragma unroll
    for (int am = 0; am < 4; am++) {
        #pragma unroll
        for (int an = 0; an < 2; an++) {
            const int l = lbase + am * 16;
            const int n = nbase + an * 8;
            const size_t o0 = ((size_t)b * L_ + l) * N_ + n;
            const size_t o1 = o0 + 8 * N_;
            float v0 = acc[am][an][0] + B0[o0];
            float v1 = acc[am][an][1] + B0[o0 + 1];
            float v2 = acc[am][an][2] + B0[o1];
            float v3 = acc[am][an][3] + B0[o1 + 1];
            if (pred) {
                v0 += pred[o0]; v1 += pred[o0 + 1];
                v2 += pred[o1]; v3 += pred[o1 + 1];
            }
            if (LAST) {
                *(float2*)&f32out[o0] = make_float2(v0, v1);
                *(float2*)&f32out[o1] = make_float2(v2, v3);
            } else {
                __nv_bfloat16 h0 = __float2bfloat16(v0), h1 = __float2bfloat16(v1);
                __nv_bfloat16 h2 = __float2bfloat16(v2), h3 = __float2bfloat16(v3);
                __nv_bfloat162 lo01 = __floats2bfloat162_rn(v0 - __bfloat162float(h0),
                                                            v1 - __bfloat162float(h1));
                __nv_bfloat162 lo23 = __floats2bfloat162_rn(v2 - __bfloat162float(h2),
                                                            v3 - __bfloat162float(h3));
                uint32_t hp0 = (uint32_t)__bfloat16_as_ushort(h0) |
                               ((uint32_t)__bfloat16_as_ushort(h1) << 16);
                uint32_t hp1 = (uint32_t)__bfloat16_as_ushort(h2) |
                               ((uint32_t)__bfloat16_as_ushort(h3) << 16);
                *(uint32_t*)&uh_out[o0] = hp0;
                *(uint32_t*)&uh_out[o1] = hp1;
                *(uint32_t*)&ul_out[o0] = *reinterpret_cast<uint32_t*>(&lo01);
                *(uint32_t*)&ul_out[o1] = *reinterpret_cast<uint32_t*>(&lo23);
            }
        }
    }
}

// ---------------------------------------------------------------------------
extern "C" void kernel_launch(void* const* d_in, const int* in_sizes, int n_in,
                              void* d_out, int out_size)
{
    const float* samples = (const float*)d_in[0];  // [8,1024,3072]
    const float* label   = (const float*)d_in[1];  // [8,1024,64]
    const float* predict = (const float*)d_in[2];  // [8,1024,64]
    const float* W       = (const float*)d_in[3];  // [1024,3072]
    const float* bproj   = (const float*)d_in[4];  // [1024]
    float* out = (float*)d_out;                    // [8,1024,64]

    __nv_bfloat16 *smph, *smpl, *Wh, *Wl, *sh, *sl, *uh1, *ul1, *uh2, *ul2;
    float *A, *B0;
    cudaGetSymbolAddress((void**)&smph, g_smp_hi);
    cudaGetSymbolAddress((void**)&smpl, g_smp_lo);
    cudaGetSymbolAddress((void**)&Wh,   g_W_hi);
    cudaGetSymbolAddress((void**)&Wl,   g_W_lo);
    cudaGetSymbolAddress((void**)&sh,   g_s_hi);
    cudaGetSymbolAddress((void**)&sl,   g_s_lo);
    cudaGetSymbolAddress((void**)&A,    g_A);
    cudaGetSymbolAddress((void**)&B0,   g_B0);
    cudaGetSymbolAddress((void**)&uh1,  g_uh1);
    cudaGetSymbolAddress((void**)&ul1,  g_ul1);
    cudaGetSymbolAddress((void**)&uh2,  g_uh2);
    cudaGetSymbolAddress((void**)&ul2,  g_ul2);

    cudaFuncSetAttribute(gemm_proj, cudaFuncAttributeMaxDynamicSharedMemorySize, P_SMEM);
    cudaFuncSetAttribute(gemm_sym,  cudaFuncAttributeMaxDynamicSharedMemorySize, S_SMEM);
    cudaFuncSetAttribute(iter_mma<0>, cudaFuncAttributeMaxDynamicSharedMemorySize, IT_SMEM);
    cudaFuncSetAttribute(iter_mma<1>, cudaFuncAttributeMaxDynamicSharedMemorySize, IT_SMEM);

    {
        int n4 = (B_ * L_ * K3_) / 4;
        split_kernel<<<(n4 + 255) / 256, 256>>>(samples, smph, smpl, n4);
        int w4 = (H_ * K3_) / 4;
        split_kernel<<<(w4 + 255) / 256, 256>>>(W, Wh, Wl, w4);
    }

    gemm_proj<<<dim3(H_ / 256, (B_ * L_) / 128, 1), 256, P_SMEM>>>(
        smph, smpl, Wh, Wl, bproj, sh, sl);

    gemm_sym<<<dim3(36, 1, B_), 256, S_SMEM>>>(sh, sl, A);

    softmax_kernel<<<dim3(L_, B_), 256>>>(A, sh, sl);

    b0_kernel<<<B_, 1024>>>(label, B0, uh1, ul1);

    dim3 ig(L_ / 128, 1, B_);
    iter_mma<0><<<ig, 256, IT_SMEM>>>(sh, sl, uh1, ul1, B0, nullptr,  uh2, ul2, nullptr); // t=2
    iter_mma<0><<<ig, 256, IT_SMEM>>>(sh, sl, uh2, ul2, B0, predict,  uh1, ul1, nullptr); // t=3
    iter_mma<0><<<ig, 256, IT_SMEM>>>(sh, sl, uh1, ul1, B0, nullptr,  uh2, ul2, nullptr); // t=4
    iter_mma<0><<<ig, 256, IT_SMEM>>>(sh, sl, uh2, ul2, B0, nullptr,  uh1, ul1, nullptr); // t=5
    iter_mma<1><<<ig, 256, IT_SMEM>>>(sh, sl, uh1, ul1, B0, nullptr,  nullptr, nullptr, out); // t=6
}